// round 1
// baseline (speedup 1.0000x reference)
#include <cuda_runtime.h>
#include <math.h>

#define NNODES 10000
#define KNBR   16
#define NEDGE  (NNODES * KNBR)

// ---------------- scratch (static device globals; no allocation) ------------
__device__ float g_h[NEDGE * 64];      // gelu MLP hidden, [e][c]
__device__ float g_tmp[NEDGE * 16];    // tmp16, [e][j]   (j = m*2+l)
__device__ float g_w2t[768 * 64];      // W2 transposed: [j][c][i48]
__device__ float g_b2lt[768];          // b2_lin transposed: [j][i48]
__device__ float g_sc[NEDGE * 4];      // per-edge head scores
__device__ float g_v[NEDGE * 32];      // per-edge v values [m][d]

// ---------------- kernel 0: weight transposes -------------------------------
__global__ void k0_transpose(const float* __restrict__ W2,
                             const float* __restrict__ b2l) {
    int idx = blockIdx.x * blockDim.x + threadIdx.x;
    if (idx < 768 * 64) {
        int r = idx >> 6, c = idx & 63;     // W2 row r = i*16+j, col c
        int i = r >> 4, j = r & 15;
        g_w2t[(j * 64 + c) * 48 + i] = W2[idx];
    }
    if (idx < 768) {
        int i = idx >> 4, j = idx & 15;
        g_b2lt[j * 48 + i] = b2l[idx];
    }
}

// ---------------- kernel 1: per-edge prep (h = gelu(W1 ef + b), tmp) --------
// 128 threads = 4 warps; each warp handles 16 consecutive edges.
__global__ void k1_prep(const float* __restrict__ ef,
                        const float* __restrict__ W1,
                        const float* __restrict__ b1lin,
                        const float* __restrict__ f,
                        const int*   __restrict__ nidx,
                        const float* __restrict__ b1) {
    __shared__ float W1s[64 * 33];   // padded rows -> conflict-free
    int tid = threadIdx.x;
    for (int idx = tid; idx < 2048; idx += 128)
        W1s[(idx >> 5) * 33 + (idx & 31)] = W1[idx];
    __syncthreads();

    int warp = tid >> 5, lane = tid & 31;
    int ebase = (blockIdx.x * 4 + warp) * 16;
    float bl0 = b1lin[lane], bl1 = b1lin[lane + 32];

    for (int it = 0; it < 16; ++it) {
        int e = ebase + it;
        float efr = ef[(size_t)e * 32 + lane];
        float a0 = bl0, a1 = bl1;
#pragma unroll
        for (int d = 0; d < 32; ++d) {
            float ed = __shfl_sync(0xffffffffu, efr, d);
            a0 = fmaf(W1s[lane * 33 + d], ed, a0);
            a1 = fmaf(W1s[(lane + 32) * 33 + d], ed, a1);
        }
        // exact gelu
        a0 = a0 * 0.5f * (1.0f + erff(a0 * 0.70710678118654752f));
        a1 = a1 * 0.5f * (1.0f + erff(a1 * 0.70710678118654752f));
        g_h[(size_t)e * 64 + lane]      = a0;
        g_h[(size_t)e * 64 + lane + 32] = a1;

        if (lane < 16) {   // tmp[j = m*2+l] = sum_d f_src[m,d]*b1f[d,l]
            int m = lane >> 1, l = lane & 1;
            int nbr = nidx[e];
            const float* frow = f + (size_t)nbr * 32 + m * 4;
            const float* brow = b1 + (size_t)e * 8;
            float t = 0.f;
#pragma unroll
            for (int d = 0; d < 4; ++d)
                t = fmaf(frow[d], brow[d * 2 + l], t);
            g_tmp[(size_t)e * 16 + lane] = t;
        }
    }
}

// ---------------- kernel 2: fused W2 GEMM + tmp contraction + edge epilogue -
// CTA: 192 threads = 6 (i) x 32 (edge). Tile: 128 edges x 48 i-outputs.
// smem: h_s[64][132] | tmp_s[16][132] | w2_s[64][48]; out_s overlays h_s.
#define K2_SMEM_FLOATS (64 * 132 + 16 * 132 + 64 * 48)
#define K2_SMEM_BYTES  (K2_SMEM_FLOATS * 4)

__global__ void __launch_bounds__(192, 3)
k2_gemm(const float* __restrict__ b2) {
    extern __shared__ float smem[];
    float* h_s   = smem;                       // 64*132
    float* tmp_s = smem + 64 * 132;            // 16*132
    float* w2_s  = smem + 64 * 132 + 16 * 132; // 64*48
    float* out_s = smem;                       // overlay (128*49 <= 64*132)

    const int tid = threadIdx.x;
    const int te  = tid & 31;   // edge group: edges te*4 .. te*4+3
    const int ti  = tid >> 5;   // i group: i = ti*8 + ii
    const int e0  = blockIdx.x * 128;

    // stage h tile transposed: h_s[c][e]
    for (int idx = tid; idx < 2048; idx += 192) {
        int e = idx >> 4, q = idx & 15;
        float4 v = *reinterpret_cast<const float4*>(&g_h[(size_t)(e0 + e) * 64 + q * 4]);
        h_s[(q * 4 + 0) * 132 + e] = v.x;
        h_s[(q * 4 + 1) * 132 + e] = v.y;
        h_s[(q * 4 + 2) * 132 + e] = v.z;
        h_s[(q * 4 + 3) * 132 + e] = v.w;
    }
    // stage tmp tile transposed: tmp_s[j][e]
    for (int idx = tid; idx < 2048; idx += 192) {
        int e = idx >> 4, j = idx & 15;
        tmp_s[j * 132 + e] = g_tmp[(size_t)(e0 + e) * 16 + j];
    }

    float out[8][4];
#pragma unroll
    for (int ii = 0; ii < 8; ++ii)
#pragma unroll
        for (int ee = 0; ee < 4; ++ee) out[ii][ee] = 0.f;

#pragma unroll 1
    for (int j = 0; j < 16; ++j) {
        __syncthreads();   // protect w2_s from previous iteration's readers
        {
            const float4* src = reinterpret_cast<const float4*>(g_w2t + j * 3072);
            float4* dst = reinterpret_cast<float4*>(w2_s);
            for (int idx = tid; idx < 768; idx += 192) dst[idx] = src[idx];
        }
        __syncthreads();

        float4 tj = *reinterpret_cast<const float4*>(&tmp_s[j * 132 + te * 4]);

        float acc[8][4];
#pragma unroll
        for (int ii = 0; ii < 8; ++ii) {
            float bl = g_b2lt[j * 48 + ti * 8 + ii];
            acc[ii][0] = bl; acc[ii][1] = bl; acc[ii][2] = bl; acc[ii][3] = bl;
        }

#pragma unroll 16
        for (int c = 0; c < 64; ++c) {
            float4 hv = *reinterpret_cast<const float4*>(&h_s[c * 132 + te * 4]);
            float4 w0 = *reinterpret_cast<const float4*>(&w2_s[c * 48 + ti * 8]);
            float4 w1 = *reinterpret_cast<const float4*>(&w2_s[c * 48 + ti * 8 + 4]);
            const float ws[8] = {w0.x, w0.y, w0.z, w0.w, w1.x, w1.y, w1.z, w1.w};
#pragma unroll
            for (int ii = 0; ii < 8; ++ii) {
                acc[ii][0] = fmaf(ws[ii], hv.x, acc[ii][0]);
                acc[ii][1] = fmaf(ws[ii], hv.y, acc[ii][1]);
                acc[ii][2] = fmaf(ws[ii], hv.z, acc[ii][2]);
                acc[ii][3] = fmaf(ws[ii], hv.w, acc[ii][3]);
            }
        }

#pragma unroll
        for (int ii = 0; ii < 8; ++ii) {
            out[ii][0] = fmaf(tj.x, acc[ii][0], out[ii][0]);
            out[ii][1] = fmaf(tj.y, acc[ii][1], out[ii][1]);
            out[ii][2] = fmaf(tj.z, acc[ii][2], out[ii][2]);
            out[ii][3] = fmaf(tj.w, acc[ii][3], out[ii][3]);
        }
    }

    __syncthreads();  // all h_s reads done -> safe to overlay out_s
#pragma unroll
    for (int ii = 0; ii < 8; ++ii)
#pragma unroll
        for (int ee = 0; ee < 4; ++ee)
            out_s[(te * 4 + ee) * 49 + ti * 8 + ii] = out[ii][ee];
    __syncthreads();

    // per-edge epilogue: qkv = out48.reshape(24,2) @ b2f -> scores + v
    if (tid < 128) {
        int e = e0 + tid;
        const float* o48 = &out_s[tid * 49];
        float bb[8];
#pragma unroll
        for (int x = 0; x < 8; ++x) bb[x] = b2[(size_t)e * 8 + x];

#pragma unroll
        for (int h = 0; h < 4; ++h) {
            float s = 0.f;
#pragma unroll
            for (int mm = 0; mm < 2; ++mm) {
                int m = 2 * h + mm;
#pragma unroll
                for (int d = 0; d < 4; ++d) {
                    float q = o48[m * 2]       * bb[d] + o48[m * 2 + 1]       * bb[4 + d];
                    float k = o48[(8 + m) * 2] * bb[d] + o48[(8 + m) * 2 + 1] * bb[4 + d];
                    s = fmaf(q, k, s);
                }
            }
            g_sc[(size_t)e * 4 + h] = s * 0.35355339059327376f;  // 8^-0.5
        }
#pragma unroll
        for (int m = 0; m < 8; ++m)
#pragma unroll
            for (int d = 0; d < 4; ++d)
                g_v[(size_t)e * 32 + m * 4 + d] =
                    o48[(16 + m) * 2] * bb[d] + o48[(16 + m) * 2 + 1] * bb[4 + d];
    }
}

// ---------------- kernel 3: softmax over K + weighted V + out-proj ----------
// one warp per node; lane: k = lane>>1, rep = lane&1 (heads rep*2, rep*2+1)
__global__ void k3_attn(const float* __restrict__ Wout,
                        const float* __restrict__ bias,
                        float* __restrict__ out) {
    __shared__ float outsm[4][33];   // per-warp out[m][d] (32) + pad
    int tid  = threadIdx.x;
    int warp = tid >> 5, lane = tid & 31;
    int n = blockIdx.x * 4 + warp;

    int k = lane >> 1, rep = lane & 1;
    float2 sc2 = *reinterpret_cast<const float2*>(&g_sc[(size_t)n * 64 + k * 4 + rep * 2]);
    float s0 = sc2.x, s1 = sc2.y;

    float m0 = s0, m1 = s1;
#pragma unroll
    for (int off = 2; off < 32; off <<= 1) {
        m0 = fmaxf(m0, __shfl_xor_sync(0xffffffffu, m0, off));
        m1 = fmaxf(m1, __shfl_xor_sync(0xffffffffu, m1, off));
    }
    float e0v = expf(s0 - m0), e1v = expf(s1 - m1);
    float z0 = e0v, z1 = e1v;
#pragma unroll
    for (int off = 2; off < 32; off <<= 1) {
        z0 += __shfl_xor_sync(0xffffffffu, z0, off);
        z1 += __shfl_xor_sync(0xffffffffu, z1, off);
    }
    float a0 = e0v / z0, a1 = e1v / z1;   // attn[k][h] for h=rep*2, rep*2+1

    float po[4][4];
#pragma unroll
    for (int ml = 0; ml < 4; ++ml) {
        int m = rep * 4 + ml;            // h = m/2 = rep*2 + (ml>=2)
        float a = (ml < 2) ? a0 : a1;
        float4 vv = *reinterpret_cast<const float4*>(&g_v[(size_t)n * 512 + k * 32 + m * 4]);
        po[ml][0] = a * vv.x; po[ml][1] = a * vv.y;
        po[ml][2] = a * vv.z; po[ml][3] = a * vv.w;
    }
#pragma unroll
    for (int off = 2; off < 32; off <<= 1)
#pragma unroll
        for (int ml = 0; ml < 4; ++ml)
#pragma unroll
            for (int d = 0; d < 4; ++d)
                po[ml][d] += __shfl_xor_sync(0xffffffffu, po[ml][d], off);

    if (lane < 2) {                      // lanes 0 (rep0: m 0..3), 1 (rep1: m 4..7)
#pragma unroll
        for (int ml = 0; ml < 4; ++ml)
#pragma unroll
            for (int d = 0; d < 4; ++d)
                outsm[warp][(rep * 4 + ml) * 4 + d] = po[ml][d];
    }
    __syncwarp();

    // out-projection: d==0 uses W_out rows 0..7 (+bias), d>=1 uses rows 8..15
    int mm = lane >> 2, dd = lane & 3;
    int o = (dd == 0) ? mm : 8 + mm;
    float val = (dd == 0) ? bias[mm] : 0.f;
#pragma unroll
    for (int mp = 0; mp < 8; ++mp)
        val = fmaf(Wout[o * 8 + mp], outsm[warp][mp * 4 + dd], val);
    out[(size_t)n * 32 + lane] = val;
}

// ---------------- launcher ---------------------------------------------------
extern "C" void kernel_launch(void* const* d_in, const int* in_sizes, int n_in,
                              void* d_out, int out_size) {
    const float* b1   = (const float*)d_in[0];
    const float* b2   = (const float*)d_in[1];
    const float* ef   = (const float*)d_in[2];
    const float* f    = (const float*)d_in[3];
    const int*   nidx = (const int*)  d_in[4];
    const float* W1   = (const float*)d_in[5];
    const float* b1l  = (const float*)d_in[6];
    const float* W2   = (const float*)d_in[7];
    const float* b2l  = (const float*)d_in[8];
    const float* Wout = (const float*)d_in[9];
    const float* bias = (const float*)d_in[10];
    float* out = (float*)d_out;
    (void)in_sizes; (void)n_in; (void)out_size;

    cudaFuncSetAttribute(k2_gemm, cudaFuncAttributeMaxDynamicSharedMemorySize,
                         K2_SMEM_BYTES);

    k0_transpose<<<(768 * 64 + 255) / 256, 256>>>(W2, b2l);
    k1_prep<<<NEDGE / 64, 128>>>(ef, W1, b1l, f, nidx, b1);
    k2_gemm<<<NEDGE / 128, 192, K2_SMEM_BYTES>>>(b2);
    k3_attn<<<NNODES / 4, 128>>>(Wout, bias, out);
}

// round 3
// speedup vs baseline: 1.7531x; 1.7531x over previous
#include <cuda_runtime.h>
#include <cuda_bf16.h>
#include <math.h>
#include <stdint.h>

#define NNODES 10000
#define KNBR   16
#define NEDGE  (NNODES * KNBR)
#define NTILES (NEDGE / 128)          // 1250

// ---------------- scratch (static device globals; no allocation) ------------
__device__ __align__(16) unsigned char g_hhi[NEDGE * 128];  // h hi bf16, SW128 tiles [tile][16KB]
__device__ __align__(16) unsigned char g_hlo[NEDGE * 128];  // h lo bf16, SW128 tiles
__device__ __align__(16) unsigned char g_w2p[12 * 16384];   // W2 [chunk][hi/lo] bf16 SW128 tiles
__device__ float g_tmp[NEDGE * 16];   // tmp16 fp32, [e][j]
__device__ float g_sc[NEDGE * 4];     // per-edge head scores
__device__ float g_v[NEDGE * 32];     // per-edge v values [m][d]

// ---------------- helpers ----------------------------------------------------
__device__ __forceinline__ uint32_t sw128(uint32_t o) { return o ^ ((o >> 3) & 0x70u); }

__device__ __forceinline__ uint32_t smem_u32(const void* p) {
    uint32_t a;
    asm("{ .reg .u64 t; cvta.to.shared.u64 t, %1; cvt.u32.u64 %0, t; }" : "=r"(a) : "l"(p));
    return a;
}
__device__ __forceinline__ void ldsm_x4(uint32_t* r, uint32_t addr) {
    asm volatile("ldmatrix.sync.aligned.m8n8.x4.shared.b16 {%0,%1,%2,%3}, [%4];"
                 : "=r"(r[0]), "=r"(r[1]), "=r"(r[2]), "=r"(r[3]) : "r"(addr));
}
__device__ __forceinline__ void mma16816(float* c, const uint32_t* a, const uint32_t* b) {
    asm volatile(
        "mma.sync.aligned.m16n8k16.row.col.f32.bf16.bf16.f32 "
        "{%0,%1,%2,%3}, {%4,%5,%6,%7}, {%8,%9}, {%0,%1,%2,%3};"
        : "+f"(c[0]), "+f"(c[1]), "+f"(c[2]), "+f"(c[3])
        : "r"(a[0]), "r"(a[1]), "r"(a[2]), "r"(a[3]), "r"(b[0]), "r"(b[1]));
}

// ---------------- kernel 0: W2 split + pre-swizzle ---------------------------
// chunk ch = W2row>>7, local row n = W2row&127; tiles of 16KB (128 rows x 128B).
__global__ void k0_w2prep(const float* __restrict__ W2) {
    int idx = blockIdx.x * 256 + threadIdx.x;
    if (idx >= 768 * 64) return;
    int r = idx >> 6, c = idx & 63;
    int ch = r >> 7, n = r & 127;
    float x = W2[idx];
    __nv_bfloat16 hi = __float2bfloat16(x);
    __nv_bfloat16 lo = __float2bfloat16(x - __bfloat162float(hi));
    uint32_t off = sw128((uint32_t)(n * 128 + c * 2));
    *(__nv_bfloat16*)(g_w2p + (size_t)(ch * 2 + 0) * 16384 + off) = hi;
    *(__nv_bfloat16*)(g_w2p + (size_t)(ch * 2 + 1) * 16384 + off) = lo;
}

// ---------------- kernel 1: per-edge prep (h hi/lo bf16 swizzled, tmp) -------
__global__ void k1_prep(const float* __restrict__ ef,
                        const float* __restrict__ W1,
                        const float* __restrict__ b1lin,
                        const float* __restrict__ f,
                        const int*   __restrict__ nidx,
                        const float* __restrict__ b1) {
    __shared__ float W1s[64 * 33];
    int tid = threadIdx.x;
    for (int idx = tid; idx < 2048; idx += 128)
        W1s[(idx >> 5) * 33 + (idx & 31)] = W1[idx];
    __syncthreads();

    int warp = tid >> 5, lane = tid & 31;
    int ebase = (blockIdx.x * 4 + warp) * 16;
    float bl0 = b1lin[lane], bl1 = b1lin[lane + 32];

    for (int it = 0; it < 16; ++it) {
        int e = ebase + it;
        float efr = ef[(size_t)e * 32 + lane];
        float a0 = bl0, a1 = bl1;
#pragma unroll
        for (int d = 0; d < 32; ++d) {
            float ed = __shfl_sync(0xffffffffu, efr, d);
            a0 = fmaf(W1s[lane * 33 + d], ed, a0);
            a1 = fmaf(W1s[(lane + 32) * 33 + d], ed, a1);
        }
        a0 = a0 * 0.5f * (1.0f + erff(a0 * 0.70710678118654752f));
        a1 = a1 * 0.5f * (1.0f + erff(a1 * 0.70710678118654752f));

        int tile = e >> 7, row = e & 127;
        size_t tb = (size_t)tile * 16384;
        uint32_t o0 = sw128((uint32_t)(row * 128 + lane * 2));
        uint32_t o1 = sw128((uint32_t)(row * 128 + (lane + 32) * 2));
        __nv_bfloat16 h0 = __float2bfloat16(a0);
        __nv_bfloat16 h1 = __float2bfloat16(a1);
        *(__nv_bfloat16*)(g_hhi + tb + o0) = h0;
        *(__nv_bfloat16*)(g_hhi + tb + o1) = h1;
        *(__nv_bfloat16*)(g_hlo + tb + o0) = __float2bfloat16(a0 - __bfloat162float(h0));
        *(__nv_bfloat16*)(g_hlo + tb + o1) = __float2bfloat16(a1 - __bfloat162float(h1));

        if (lane < 16) {
            int m = lane >> 1, l = lane & 1;
            int nbr = nidx[e];
            const float* frow = f + (size_t)nbr * 32 + m * 4;
            const float* brow = b1 + (size_t)e * 8;
            float t = 0.f;
#pragma unroll
            for (int d = 0; d < 4; ++d)
                t = fmaf(frow[d], brow[d * 2 + l], t);
            g_tmp[(size_t)e * 16 + lane] = t;
        }
    }
}

// ---------------- kernel 2: HMMA split-bf16 GEMM + j-contract + epilogue -----
// smem byte offsets (B/A tiles 1024-aligned for swizzle):
#define S_TMP  0                    // 128*16 f32 = 8192
#define S_BL   8192                 // 768 f32    = 3072
#define S_BH   11264                // 16384
#define S_BLO  27648                // 16384
#define S_AHI  44032                // 16384
#define S_ALO  60416                // 16384
#define S_OUT  76800                // 128*49 f32 = 25088
#define S_TOT  101888

__global__ void __launch_bounds__(256, 2)
k2_mma(const float* __restrict__ b2, const float* __restrict__ b2l) {
    extern __shared__ __align__(1024) unsigned char smem[];
    const uint32_t sb = smem_u32(smem);
    float* tmp_s = (float*)(smem + S_TMP);
    float* bl_s  = (float*)(smem + S_BL);
    float* out_s = (float*)(smem + S_OUT);

    const int tid = threadIdx.x, wid = tid >> 5, lane = tid & 31;
    const int e0 = blockIdx.x << 7;
    const int wbase = wid * 16;          // warp's first edge row (local)

    // stage tmp (2048 f32), bl (768 f32), A hi/lo (32KB), B chunk0 (32KB)
    for (int i = tid; i < 2048; i += 256) tmp_s[i] = g_tmp[(size_t)e0 * 16 + i];
    for (int i = tid; i < 768;  i += 256) bl_s[i] = b2l[i];
    {
        const uint4* shi = (const uint4*)(g_hhi + (size_t)blockIdx.x * 16384);
        const uint4* slo = (const uint4*)(g_hlo + (size_t)blockIdx.x * 16384);
        uint4* dhi = (uint4*)(smem + S_AHI);
        uint4* dlo = (uint4*)(smem + S_ALO);
        const uint4* sB = (const uint4*)(g_w2p);
        uint4* dB = (uint4*)(smem + S_BH);
        for (int i = tid; i < 1024; i += 256) { dhi[i] = shi[i]; dlo[i] = slo[i]; }
        for (int i = tid; i < 2048; i += 256) dB[i] = sB[i];
    }
    __syncthreads();

    // A fragments: per warp, rows wbase..wbase+15, 4 k-steps, hi+lo
    uint32_t aH[16], aL[16];
    {
        uint32_t rowb = (uint32_t)(wbase + (lane & 15)) * 128 + ((lane >> 4) << 4);
#pragma unroll
        for (int s = 0; s < 4; ++s) {
            uint32_t off = sw128(rowb + 32 * s);
            ldsm_x4(&aH[4 * s], sb + S_AHI + off);
            ldsm_x4(&aL[4 * s], sb + S_ALO + off);
        }
    }

    const int er0 = wbase + (lane >> 2);   // this thread's first edge row
    const int jq  = (lane & 3) * 2;        // col offset within n-tile
    float accA = 0.f, accB = 0.f;

#pragma unroll 1
    for (int ch = 0; ch < 6; ++ch) {
#pragma unroll 2
        for (int nt = 0; nt < 16; ++nt) {
            const int nb = nt * 8;
            // B fragments: hi + lo, k 0..63 via 2 passes of ldmatrix.x4 each
            uint32_t bH[8], bL[8];
            uint32_t rb = (uint32_t)(nb + (lane & 7)) * 128 + ((lane >> 3) << 4);
#pragma unroll
            for (int p = 0; p < 2; ++p) {
                uint32_t off = sw128(rb + 64 * p);
                ldsm_x4(&bH[4 * p], sb + S_BH + off);
                ldsm_x4(&bL[4 * p], sb + S_BLO + off);
            }

            float c[4] = {0.f, 0.f, 0.f, 0.f};
#pragma unroll
            for (int s = 0; s < 4; ++s) mma16816(c, &aH[4 * s], &bH[2 * s]);
#pragma unroll
            for (int s = 0; s < 4; ++s) mma16816(c, &aL[4 * s], &bH[2 * s]);
#pragma unroll
            for (int s = 0; s < 4; ++s) mma16816(c, &aH[4 * s], &bL[2 * s]);

            // contract with tmp over this n-tile's 2 cols per thread
            const int g0 = ch * 128 + nb + jq;           // global rw col
            const int j0 = (nb & 8) + jq;                // j within 16
            float blv0 = bl_s[g0], blv1 = bl_s[g0 + 1];
            float2 t0 = *(float2*)&tmp_s[er0 * 16 + j0];
            float2 t1 = *(float2*)&tmp_s[(er0 + 8) * 16 + j0];
            accA += (c[0] + blv0) * t0.x + (c[1] + blv1) * t0.y;
            accB += (c[2] + blv0) * t1.x + (c[3] + blv1) * t1.y;

            if (nt & 1) {   // finished an i-group (16 cols)
                accA += __shfl_xor_sync(0xffffffffu, accA, 1);
                accA += __shfl_xor_sync(0xffffffffu, accA, 2);
                accB += __shfl_xor_sync(0xffffffffu, accB, 1);
                accB += __shfl_xor_sync(0xffffffffu, accB, 2);
                if ((lane & 3) == 0) {
                    int i = ch * 8 + (nt >> 1);
                    out_s[er0 * 49 + i]       = accA;
                    out_s[(er0 + 8) * 49 + i] = accB;
                }
                accA = 0.f; accB = 0.f;
            }
        }
        if (ch < 5) {   // stage next B chunk
            __syncthreads();
            const uint4* sB = (const uint4*)(g_w2p + (size_t)(ch + 1) * 32768);
            uint4* dB = (uint4*)(smem + S_BH);
            for (int i = tid; i < 2048; i += 256) dB[i] = sB[i];
            __syncthreads();
        }
    }
    __syncthreads();

    // per-edge epilogue: qkv = out48.reshape(24,2) @ b2f -> scores + v
    if (tid < 128) {
        int e = e0 + tid;
        const float* o48 = out_s + tid * 49;
        float bb[8];
#pragma unroll
        for (int x = 0; x < 8; ++x) bb[x] = b2[(size_t)e * 8 + x];

#pragma unroll
        for (int h = 0; h < 4; ++h) {
            float s = 0.f;
#pragma unroll
            for (int mm = 0; mm < 2; ++mm) {
                int m = 2 * h + mm;
#pragma unroll
                for (int d = 0; d < 4; ++d) {
                    float q = o48[m * 2]       * bb[d] + o48[m * 2 + 1]       * bb[4 + d];
                    float k = o48[(8 + m) * 2] * bb[d] + o48[(8 + m) * 2 + 1] * bb[4 + d];
                    s = fmaf(q, k, s);
                }
            }
            g_sc[(size_t)e * 4 + h] = s * 0.35355339059327376f;
        }
#pragma unroll
        for (int m = 0; m < 8; ++m)
#pragma unroll
            for (int d = 0; d < 4; ++d)
                g_v[(size_t)e * 32 + m * 4 + d] =
                    o48[(16 + m) * 2] * bb[d] + o48[(16 + m) * 2 + 1] * bb[4 + d];
    }
}

// ---------------- kernel 3: softmax over K + weighted V + out-proj ----------
__global__ void k3_attn(const float* __restrict__ Wout,
                        const float* __restrict__ bias,
                        float* __restrict__ out) {
    __shared__ float outsm[4][33];
    int tid = threadIdx.x;
    int warp = tid >> 5, lane = tid & 31;
    int n = blockIdx.x * 4 + warp;

    int k = lane >> 1, rep = lane & 1;
    float2 sc2 = *reinterpret_cast<const float2*>(&g_sc[(size_t)n * 64 + k * 4 + rep * 2]);
    float s0 = sc2.x, s1 = sc2.y;

    float m0 = s0, m1 = s1;
#pragma unroll
    for (int off = 2; off < 32; off <<= 1) {
        m0 = fmaxf(m0, __shfl_xor_sync(0xffffffffu, m0, off));
        m1 = fmaxf(m1, __shfl_xor_sync(0xffffffffu, m1, off));
    }
    float e0v = expf(s0 - m0), e1v = expf(s1 - m1);
    float z0 = e0v, z1 = e1v;
#pragma unroll
    for (int off = 2; off < 32; off <<= 1) {
        z0 += __shfl_xor_sync(0xffffffffu, z0, off);
        z1 += __shfl_xor_sync(0xffffffffu, z1, off);
    }
    float a0 = e0v / z0, a1 = e1v / z1;

    float po[4][4];
#pragma unroll
    for (int ml = 0; ml < 4; ++ml) {
        int m = rep * 4 + ml;
        float a = (ml < 2) ? a0 : a1;
        float4 vv = *reinterpret_cast<const float4*>(&g_v[(size_t)n * 512 + k * 32 + m * 4]);
        po[ml][0] = a * vv.x; po[ml][1] = a * vv.y;
        po[ml][2] = a * vv.z; po[ml][3] = a * vv.w;
    }
#pragma unroll
    for (int off = 2; off < 32; off <<= 1)
#pragma unroll
        for (int ml = 0; ml < 4; ++ml)
#pragma unroll
            for (int d = 0; d < 4; ++d)
                po[ml][d] += __shfl_xor_sync(0xffffffffu, po[ml][d], off);

    if (lane < 2) {
#pragma unroll
        for (int ml = 0; ml < 4; ++ml)
#pragma unroll
            for (int d = 0; d < 4; ++d)
                outsm[warp][(rep * 4 + ml) * 4 + d] = po[ml][d];
    }
    __syncwarp();

    int mm = lane >> 2, dd = lane & 3;
    int o = (dd == 0) ? mm : 8 + mm;
    float val = (dd == 0) ? bias[mm] : 0.f;
#pragma unroll
    for (int mp = 0; mp < 8; ++mp)
        val = fmaf(Wout[o * 8 + mp], outsm[warp][mp * 4 + dd], val);
    out[(size_t)n * 32 + lane] = val;
}

// ---------------- launcher ----------------------------------------------------
extern "C" void kernel_launch(void* const* d_in, const int* in_sizes, int n_in,
                              void* d_out, int out_size) {
    const float* b1   = (const float*)d_in[0];
    const float* b2   = (const float*)d_in[1];
    const float* ef   = (const float*)d_in[2];
    const float* f    = (const float*)d_in[3];
    const int*   nidx = (const int*)  d_in[4];
    const float* W1   = (const float*)d_in[5];
    const float* b1l  = (const float*)d_in[6];
    const float* W2   = (const float*)d_in[7];
    const float* b2l  = (const float*)d_in[8];
    const float* Wout = (const float*)d_in[9];
    const float* bias = (const float*)d_in[10];
    float* out = (float*)d_out;
    (void)in_sizes; (void)n_in; (void)out_size;

    cudaFuncSetAttribute(k2_mma, cudaFuncAttributeMaxDynamicSharedMemorySize, S_TOT);

    k0_w2prep<<<(768 * 64 + 255) / 256, 256>>>(W2);
    k1_prep<<<NEDGE / 64, 128>>>(ef, W1, b1l, f, nidx, b1);
    k2_mma<<<NTILES, 256, S_TOT>>>(b2, b2l);
    k3_attn<<<NNODES / 4, 128>>>(Wout, bias, out);
}

// round 4
// speedup vs baseline: 1.8920x; 1.0792x over previous
#include <cuda_runtime.h>
#include <cuda_bf16.h>
#include <math.h>
#include <stdint.h>

#define NNODES 10000
#define KNBR   16
#define NEDGE  (NNODES * KNBR)
#define NTILES (NEDGE / 128)          // 1250

// ---------------- scratch (static device globals; no allocation) ------------
__device__ __align__(16) unsigned char g_hhi[NEDGE * 128];  // h hi bf16, SW128 tiles [tile][16KB]
__device__ __align__(16) unsigned char g_hlo[NEDGE * 128];  // h lo bf16, SW128 tiles
__device__ __align__(16) unsigned char g_w2p[12 * 16384];   // W2 [chunk][hi/lo] bf16 SW128 tiles
__device__ float g_tmp[NEDGE * 16];   // tmp16 fp32, [e][j]
__device__ float g_sc[NEDGE * 4];     // per-edge head scores
__device__ float g_v[NEDGE * 32];     // per-edge v values [m][d]

// ---------------- helpers ----------------------------------------------------
__device__ __forceinline__ uint32_t sw128(uint32_t o) { return o ^ ((o >> 3) & 0x70u); }

__device__ __forceinline__ uint32_t smem_u32(const void* p) {
    uint32_t a;
    asm("{ .reg .u64 t; cvta.to.shared.u64 t, %1; cvt.u32.u64 %0, t; }" : "=r"(a) : "l"(p));
    return a;
}
__device__ __forceinline__ void ldsm_x4(uint32_t* r, uint32_t addr) {
    asm volatile("ldmatrix.sync.aligned.m8n8.x4.shared.b16 {%0,%1,%2,%3}, [%4];"
                 : "=r"(r[0]), "=r"(r[1]), "=r"(r[2]), "=r"(r[3]) : "r"(addr));
}
__device__ __forceinline__ void mma16816(float* c, const uint32_t* a, const uint32_t* b) {
    asm volatile(
        "mma.sync.aligned.m16n8k16.row.col.f32.bf16.bf16.f32 "
        "{%0,%1,%2,%3}, {%4,%5,%6,%7}, {%8,%9}, {%0,%1,%2,%3};"
        : "+f"(c[0]), "+f"(c[1]), "+f"(c[2]), "+f"(c[3])
        : "r"(a[0]), "r"(a[1]), "r"(a[2]), "r"(a[3]), "r"(b[0]), "r"(b[1]));
}
__device__ __forceinline__ void cpa16(uint32_t dst, const void* src) {
    asm volatile("cp.async.cg.shared.global [%0], [%1], 16;" :: "r"(dst), "l"(src));
}
#define CPA_COMMIT() asm volatile("cp.async.commit_group;" ::: "memory")
#define CPA_WAIT0()  asm volatile("cp.async.wait_group 0;" ::: "memory")

// ---------------- kernel 0: W2 split + pre-swizzle ---------------------------
__global__ void k0_w2prep(const float* __restrict__ W2) {
    int idx = blockIdx.x * 256 + threadIdx.x;
    if (idx >= 768 * 64) return;
    int r = idx >> 6, c = idx & 63;
    int ch = r >> 7, n = r & 127;
    float x = W2[idx];
    __nv_bfloat16 hi = __float2bfloat16(x);
    __nv_bfloat16 lo = __float2bfloat16(x - __bfloat162float(hi));
    uint32_t off = sw128((uint32_t)(n * 128 + c * 2));
    *(__nv_bfloat16*)(g_w2p + (size_t)(ch * 2 + 0) * 16384 + off) = hi;
    *(__nv_bfloat16*)(g_w2p + (size_t)(ch * 2 + 1) * 16384 + off) = lo;
}

// ---------------- kernel 1: per-edge prep (h hi/lo bf16 swizzled, tmp) -------
__global__ void k1_prep(const float* __restrict__ ef,
                        const float* __restrict__ W1,
                        const float* __restrict__ b1lin,
                        const float* __restrict__ f,
                        const int*   __restrict__ nidx,
                        const float* __restrict__ b1) {
    __shared__ float W1s[64 * 33];
    int tid = threadIdx.x;
    for (int idx = tid; idx < 2048; idx += 128)
        W1s[(idx >> 5) * 33 + (idx & 31)] = W1[idx];
    __syncthreads();

    int warp = tid >> 5, lane = tid & 31;
    int ebase = (blockIdx.x * 4 + warp) * 16;
    float bl0 = b1lin[lane], bl1 = b1lin[lane + 32];

    for (int it = 0; it < 16; ++it) {
        int e = ebase + it;
        float efr = ef[(size_t)e * 32 + lane];
        float a0 = bl0, a1 = bl1;
#pragma unroll
        for (int d = 0; d < 32; ++d) {
            float ed = __shfl_sync(0xffffffffu, efr, d);
            a0 = fmaf(W1s[lane * 33 + d], ed, a0);
            a1 = fmaf(W1s[(lane + 32) * 33 + d], ed, a1);
        }
        a0 = a0 * 0.5f * (1.0f + erff(a0 * 0.70710678118654752f));
        a1 = a1 * 0.5f * (1.0f + erff(a1 * 0.70710678118654752f));

        int tile = e >> 7, row = e & 127;
        size_t tb = (size_t)tile * 16384;
        uint32_t o0 = sw128((uint32_t)(row * 128 + lane * 2));
        uint32_t o1 = sw128((uint32_t)(row * 128 + (lane + 32) * 2));
        __nv_bfloat16 h0 = __float2bfloat16(a0);
        __nv_bfloat16 h1 = __float2bfloat16(a1);
        *(__nv_bfloat16*)(g_hhi + tb + o0) = h0;
        *(__nv_bfloat16*)(g_hhi + tb + o1) = h1;
        *(__nv_bfloat16*)(g_hlo + tb + o0) = __float2bfloat16(a0 - __bfloat162float(h0));
        *(__nv_bfloat16*)(g_hlo + tb + o1) = __float2bfloat16(a1 - __bfloat162float(h1));

        if (lane < 16) {
            int m = lane >> 1, l = lane & 1;
            int nbr = nidx[e];
            const float* frow = f + (size_t)nbr * 32 + m * 4;
            const float* brow = b1 + (size_t)e * 8;
            float t = 0.f;
#pragma unroll
            for (int d = 0; d < 4; ++d)
                t = fmaf(frow[d], brow[d * 2 + l], t);
            g_tmp[(size_t)e * 16 + lane] = t;
        }
    }
}

// ---------------- kernel 2: HMMA split-bf16 GEMM + j-contract + epilogue -----
// smem: tmp | bl | B buf0 (32KB) | B buf1 (32KB; A staged here first) | out
#define S_TMP  0                    // 8192
#define S_BL   8192                 // 3072
#define S_B0   11264                // 32768
#define S_B1   44032                // 32768
#define S_OUT  76800                // 25088
#define S_TOT  101888

__global__ void __launch_bounds__(256, 2)
k2_mma(const float* __restrict__ b2, const float* __restrict__ b2l) {
    extern __shared__ __align__(1024) unsigned char smem[];
    const uint32_t sb = smem_u32(smem);
    float* tmp_s = (float*)(smem + S_TMP);
    float* bl_s  = (float*)(smem + S_BL);
    float* out_s = (float*)(smem + S_OUT);

    const int tid = threadIdx.x, wid = tid >> 5, lane = tid & 31;
    const int e0 = blockIdx.x << 7;
    const int wbase = wid * 16;

    // initial staging via cp.async: tmp(8KB), bl(3KB), A(32KB -> S_B1), B0(32KB)
    {
        const unsigned char* tsrc = (const unsigned char*)(g_tmp + (size_t)e0 * 16);
        for (int i = tid; i < 512; i += 256) cpa16(sb + S_TMP + i * 16, tsrc + i * 16);
        if (tid < 192) cpa16(sb + S_BL + tid * 16, (const unsigned char*)b2l + tid * 16);
        const unsigned char* ahi = g_hhi + (size_t)blockIdx.x * 16384;
        const unsigned char* alo = g_hlo + (size_t)blockIdx.x * 16384;
        for (int i = tid; i < 1024; i += 256) {
            cpa16(sb + S_B1 + i * 16, ahi + i * 16);             // A hi
            cpa16(sb + S_B1 + 16384 + i * 16, alo + i * 16);     // A lo
        }
        for (int i = tid; i < 2048; i += 256) cpa16(sb + S_B0 + i * 16, g_w2p + i * 16);
        CPA_COMMIT();
        CPA_WAIT0();
        __syncthreads();
    }

    // A fragments: rows wbase..wbase+15, 4 k-steps, hi+lo (from S_B1 staging)
    uint32_t aH[16], aL[16];
    {
        uint32_t rowb = (uint32_t)(wbase + (lane & 15)) * 128 + ((lane >> 4) << 4);
#pragma unroll
        for (int s = 0; s < 4; ++s) {
            uint32_t off = sw128(rowb + 32 * s);
            ldsm_x4(&aH[4 * s], sb + S_B1 + off);
            ldsm_x4(&aL[4 * s], sb + S_B1 + 16384 + off);
        }
    }
    __syncthreads();   // all warps done reading A -> S_B1 reusable

    const int er0 = wbase + (lane >> 2);
    const int jq  = (lane & 3) * 2;
    float accA = 0.f, accB = 0.f;

#pragma unroll 1
    for (int ch = 0; ch < 6; ++ch) {
        const uint32_t bufC = (ch & 1) ? (sb + S_B1) : (sb + S_B0);
        // prefetch next chunk into the other buffer (overlapped with compute)
        if (ch < 5) {
            uint32_t bufN = (ch & 1) ? (sb + S_B0) : (sb + S_B1);
            const unsigned char* src = g_w2p + (size_t)(ch + 1) * 32768;
            for (int i = tid; i < 2048; i += 256) cpa16(bufN + i * 16, src + i * 16);
            CPA_COMMIT();
        }

#pragma unroll 2
        for (int nt = 0; nt < 16; ++nt) {
            const int nb = nt * 8;
            uint32_t bH[8], bL[8];
            uint32_t rb = (uint32_t)(nb + (lane & 7)) * 128 + ((lane >> 3) << 4);
#pragma unroll
            for (int p = 0; p < 2; ++p) {
                uint32_t off = sw128(rb + 64 * p);
                ldsm_x4(&bH[4 * p], bufC + off);
                ldsm_x4(&bL[4 * p], bufC + 16384 + off);
            }

            // 3 independent accumulation chains, interleaved issue
            float c0[4] = {0,0,0,0}, c1[4] = {0,0,0,0}, c2[4] = {0,0,0,0};
#pragma unroll
            for (int s = 0; s < 4; ++s) {
                mma16816(c0, &aH[4 * s], &bH[2 * s]);
                mma16816(c1, &aL[4 * s], &bH[2 * s]);
                mma16816(c2, &aH[4 * s], &bL[2 * s]);
            }

            const int g0 = ch * 128 + nb + jq;
            const int j0 = (nb & 8) + jq;
            float blv0 = bl_s[g0], blv1 = bl_s[g0 + 1];
            float2 t0 = *(float2*)&tmp_s[er0 * 16 + j0];
            float2 t1 = *(float2*)&tmp_s[(er0 + 8) * 16 + j0];
            accA += (c0[0] + c1[0] + c2[0] + blv0) * t0.x
                  + (c0[1] + c1[1] + c2[1] + blv1) * t0.y;
            accB += (c0[2] + c1[2] + c2[2] + blv0) * t1.x
                  + (c0[3] + c1[3] + c2[3] + blv1) * t1.y;

            if (nt & 1) {
                accA += __shfl_xor_sync(0xffffffffu, accA, 1);
                accA += __shfl_xor_sync(0xffffffffu, accA, 2);
                accB += __shfl_xor_sync(0xffffffffu, accB, 1);
                accB += __shfl_xor_sync(0xffffffffu, accB, 2);
                if ((lane & 3) == 0) {
                    int i = ch * 8 + (nt >> 1);
                    out_s[er0 * 49 + i]       = accA;
                    out_s[(er0 + 8) * 49 + i] = accB;
                }
                accA = 0.f; accB = 0.f;
            }
        }

        if (ch < 5) {
            CPA_WAIT0();
            __syncthreads();
        }
    }
    __syncthreads();

    // per-edge epilogue: qkv = out48.reshape(24,2) @ b2f -> scores + v
    if (tid < 128) {
        int e = e0 + tid;
        const float* o48 = out_s + tid * 49;
        float bb[8];
#pragma unroll
        for (int x = 0; x < 8; ++x) bb[x] = b2[(size_t)e * 8 + x];

#pragma unroll
        for (int h = 0; h < 4; ++h) {
            float s = 0.f;
#pragma unroll
            for (int mm = 0; mm < 2; ++mm) {
                int m = 2 * h + mm;
#pragma unroll
                for (int d = 0; d < 4; ++d) {
                    float q = o48[m * 2]       * bb[d] + o48[m * 2 + 1]       * bb[4 + d];
                    float k = o48[(8 + m) * 2] * bb[d] + o48[(8 + m) * 2 + 1] * bb[4 + d];
                    s = fmaf(q, k, s);
                }
            }
            g_sc[(size_t)e * 4 + h] = s * 0.35355339059327376f;
        }
#pragma unroll
        for (int m = 0; m < 8; ++m)
#pragma unroll
            for (int d = 0; d < 4; ++d)
                g_v[(size_t)e * 32 + m * 4 + d] =
                    o48[(16 + m) * 2] * bb[d] + o48[(16 + m) * 2 + 1] * bb[4 + d];
    }
}

// ---------------- kernel 3: softmax over K + weighted V + out-proj ----------
// one warp per node; coalesced g_v reads (4 x 128B per node).
__global__ void k3_attn(const float* __restrict__ Wout,
                        const float* __restrict__ bias,
                        float* __restrict__ out) {
    __shared__ float outsm[4][33];
    int tid = threadIdx.x;
    int warp = tid >> 5, lane = tid & 31;
    int n = blockIdx.x * 4 + warp;

    // scores: lane -> (k = lane>>1, head pair = lane&1)
    float2 sc2 = *reinterpret_cast<const float2*>(&g_sc[(size_t)n * 64 + lane * 2]);
    float s0 = sc2.x, s1 = sc2.y;

    float m0 = s0, m1 = s1;
#pragma unroll
    for (int off = 2; off < 32; off <<= 1) {
        m0 = fmaxf(m0, __shfl_xor_sync(0xffffffffu, m0, off));
        m1 = fmaxf(m1, __shfl_xor_sync(0xffffffffu, m1, off));
    }
    float e0v = expf(s0 - m0), e1v = expf(s1 - m1);
    float z0 = e0v, z1 = e1v;
#pragma unroll
    for (int off = 2; off < 32; off <<= 1) {
        z0 += __shfl_xor_sync(0xffffffffu, z0, off);
        z1 += __shfl_xor_sync(0xffffffffu, z1, off);
    }
    float a0 = e0v / z0, a1 = e1v / z1;   // attn[k=lane>>1][h = 2*(lane&1) + {0,1}]

    // v: coalesced. iteration it: lane holds v[n, k=it*4+(lane>>3), m=lane&7, d=0..3]
    const int m_mine = lane & 7;
    const int hsel   = (m_mine >> 1) & 1;          // h&1 for h = m>>1
    float r[4] = {0.f, 0.f, 0.f, 0.f};
#pragma unroll
    for (int it = 0; it < 4; ++it) {
        float4 vv = *reinterpret_cast<const float4*>(
            &g_v[(size_t)n * 512 + it * 128 + lane * 4]);
        // attn[k][h] lives at lane' = k*2 + (h>>1), component h&1
        int lsrc = 8 * it + ((lane >> 3) << 1) + ((lane >> 2) & 1);
        float av0 = __shfl_sync(0xffffffffu, a0, lsrc);
        float av1 = __shfl_sync(0xffffffffu, a1, lsrc);
        float a = hsel ? av1 : av0;
        r[0] = fmaf(a, vv.x, r[0]);
        r[1] = fmaf(a, vv.y, r[1]);
        r[2] = fmaf(a, vv.z, r[2]);
        r[3] = fmaf(a, vv.w, r[3]);
    }
    // reduce over k_local = lane>>3 (bits 3,4)
#pragma unroll
    for (int off = 8; off < 32; off <<= 1)
#pragma unroll
        for (int d = 0; d < 4; ++d)
            r[d] += __shfl_xor_sync(0xffffffffu, r[d], off);

    if (lane < 8) {
#pragma unroll
        for (int d = 0; d < 4; ++d)
            outsm[warp][m_mine * 4 + d] = r[d];
    }
    __syncwarp();

    // out-projection: d==0 uses W_out rows 0..7 (+bias), d>=1 uses rows 8..15
    int mm = lane >> 2, dd = lane & 3;
    int o = (dd == 0) ? mm : 8 + mm;
    float val = (dd == 0) ? bias[mm] : 0.f;
#pragma unroll
    for (int mp = 0; mp < 8; ++mp)
        val = fmaf(Wout[o * 8 + mp], outsm[warp][mp * 4 + dd], val);
    out[(size_t)n * 32 + lane] = val;
}

// ---------------- launcher ----------------------------------------------------
extern "C" void kernel_launch(void* const* d_in, const int* in_sizes, int n_in,
                              void* d_out, int out_size) {
    const float* b1   = (const float*)d_in[0];
    const float* b2   = (const float*)d_in[1];
    const float* ef   = (const float*)d_in[2];
    const float* f    = (const float*)d_in[3];
    const int*   nidx = (const int*)  d_in[4];
    const float* W1   = (const float*)d_in[5];
    const float* b1l  = (const float*)d_in[6];
    const float* W2   = (const float*)d_in[7];
    const float* b2l  = (const float*)d_in[8];
    const float* Wout = (const float*)d_in[9];
    const float* bias = (const float*)d_in[10];
    float* out = (float*)d_out;
    (void)in_sizes; (void)n_in; (void)out_size;

    cudaFuncSetAttribute(k2_mma, cudaFuncAttributeMaxDynamicSharedMemorySize, S_TOT);

    k0_w2prep<<<(768 * 64 + 255) / 256, 256>>>(W2);
    k1_prep<<<NEDGE / 64, 128>>>(ef, W1, b1l, f, nidx, b1);
    k2_mma<<<NTILES, 256, S_TOT>>>(b2, b2l);
    k3_attn<<<NNODES / 4, 128>>>(Wout, bias, out);
}

// round 5
// speedup vs baseline: 2.0658x; 1.0919x over previous
#include <cuda_runtime.h>
#include <cuda_fp16.h>
#include <math.h>
#include <stdint.h>

#define NNODES 10000
#define KNBR   16
#define NEDGE  (NNODES * KNBR)
#define NTILES (NEDGE / 128)          // 1250

// ---------------- scratch (static device globals; no allocation) ------------
__device__ __align__(16) unsigned char g_hh[NEDGE * 128];   // h fp16, SW128 tiles [tile][16KB]
__device__ __align__(16) unsigned char g_w2p[12 * 16384];   // W2 [chunk][hi/lo] fp16 SW128 tiles
__device__ float g_tmp[NEDGE * 16];   // tmp16 fp32, [e][j]
__device__ float g_sc[NEDGE * 4];     // per-edge head scores
__device__ float g_v[NEDGE * 32];     // per-edge v values [m][d]

// ---------------- helpers ----------------------------------------------------
__device__ __forceinline__ uint32_t sw128(uint32_t o) { return o ^ ((o >> 3) & 0x70u); }

__device__ __forceinline__ uint32_t smem_u32(const void* p) {
    uint32_t a;
    asm("{ .reg .u64 t; cvta.to.shared.u64 t, %1; cvt.u32.u64 %0, t; }" : "=r"(a) : "l"(p));
    return a;
}
__device__ __forceinline__ void ldsm_x4(uint32_t* r, uint32_t addr) {
    asm volatile("ldmatrix.sync.aligned.m8n8.x4.shared.b16 {%0,%1,%2,%3}, [%4];"
                 : "=r"(r[0]), "=r"(r[1]), "=r"(r[2]), "=r"(r[3]) : "r"(addr));
}
__device__ __forceinline__ void mma16816h(float* c, const uint32_t* a, const uint32_t* b) {
    asm volatile(
        "mma.sync.aligned.m16n8k16.row.col.f32.f16.f16.f32 "
        "{%0,%1,%2,%3}, {%4,%5,%6,%7}, {%8,%9}, {%0,%1,%2,%3};"
        : "+f"(c[0]), "+f"(c[1]), "+f"(c[2]), "+f"(c[3])
        : "r"(a[0]), "r"(a[1]), "r"(a[2]), "r"(a[3]), "r"(b[0]), "r"(b[1]));
}
__device__ __forceinline__ void cpa16(uint32_t dst, const void* src) {
    asm volatile("cp.async.cg.shared.global [%0], [%1], 16;" :: "r"(dst), "l"(src));
}
#define CPA_COMMIT() asm volatile("cp.async.commit_group;" ::: "memory")
#define CPA_WAIT0()  asm volatile("cp.async.wait_group 0;" ::: "memory")

// ---------------- kernel 0: W2 fp16 2-term split + pre-swizzle ---------------
__global__ void k0_w2prep(const float* __restrict__ W2) {
    int idx = blockIdx.x * 256 + threadIdx.x;
    if (idx >= 768 * 64) return;
    int r = idx >> 6, c = idx & 63;
    int ch = r >> 7, n = r & 127;
    float x = W2[idx];
    __half hi = __float2half_rn(x);
    __half lo = __float2half_rn(x - __half2float(hi));
    uint32_t off = sw128((uint32_t)(n * 128 + c * 2));
    *(__half*)(g_w2p + (size_t)(ch * 2 + 0) * 16384 + off) = hi;
    *(__half*)(g_w2p + (size_t)(ch * 2 + 1) * 16384 + off) = lo;
}

// ---------------- kernel 1: per-edge prep (h fp16 swizzled, tmp) -------------
__global__ void k1_prep(const float* __restrict__ ef,
                        const float* __restrict__ W1,
                        const float* __restrict__ b1lin,
                        const float* __restrict__ f,
                        const int*   __restrict__ nidx,
                        const float* __restrict__ b1) {
    __shared__ float W1s[64 * 33];
    int tid = threadIdx.x;
    for (int idx = tid; idx < 2048; idx += 128)
        W1s[(idx >> 5) * 33 + (idx & 31)] = W1[idx];
    __syncthreads();

    int warp = tid >> 5, lane = tid & 31;
    int ebase = (blockIdx.x * 4 + warp) * 16;
    float bl0 = b1lin[lane], bl1 = b1lin[lane + 32];

    for (int it = 0; it < 16; ++it) {
        int e = ebase + it;
        float efr = ef[(size_t)e * 32 + lane];
        float a0 = bl0, a1 = bl1;
#pragma unroll
        for (int d = 0; d < 32; ++d) {
            float ed = __shfl_sync(0xffffffffu, efr, d);
            a0 = fmaf(W1s[lane * 33 + d], ed, a0);
            a1 = fmaf(W1s[(lane + 32) * 33 + d], ed, a1);
        }
        a0 = a0 * 0.5f * (1.0f + erff(a0 * 0.70710678118654752f));
        a1 = a1 * 0.5f * (1.0f + erff(a1 * 0.70710678118654752f));

        int tile = e >> 7, row = e & 127;
        size_t tb = (size_t)tile * 16384;
        *(__half*)(g_hh + tb + sw128((uint32_t)(row * 128 + lane * 2)))        = __float2half_rn(a0);
        *(__half*)(g_hh + tb + sw128((uint32_t)(row * 128 + (lane + 32) * 2))) = __float2half_rn(a1);

        if (lane < 16) {
            int m = lane >> 1, l = lane & 1;
            int nbr = nidx[e];
            const float* frow = f + (size_t)nbr * 32 + m * 4;
            const float* brow = b1 + (size_t)e * 8;
            float t = 0.f;
#pragma unroll
            for (int d = 0; d < 4; ++d)
                t = fmaf(frow[d], brow[d * 2 + l], t);
            g_tmp[(size_t)e * 16 + lane] = t;
        }
    }
}

// ---------------- kernel 2: HMMA fp16 GEMM + j-contract + epilogue -----------
// smem: tmp | bl | B buf0 (32KB) | B buf1 (32KB; A staged here first) | out
#define S_TMP  0                    // 8192
#define S_BL   8192                 // 3072
#define S_B0   11264                // 32768
#define S_B1   44032                // 32768
#define S_OUT  76800                // 25088
#define S_TOT  101888

__global__ void __launch_bounds__(256, 2)
k2_mma(const float* __restrict__ b2, const float* __restrict__ b2l) {
    extern __shared__ __align__(1024) unsigned char smem[];
    const uint32_t sb = smem_u32(smem);
    float* tmp_s = (float*)(smem + S_TMP);
    float* bl_s  = (float*)(smem + S_BL);
    float* out_s = (float*)(smem + S_OUT);

    const int tid = threadIdx.x, wid = tid >> 5, lane = tid & 31;
    const int e0 = blockIdx.x << 7;
    const int wbase = wid * 16;

    // initial staging via cp.async: tmp(8KB), bl(3KB), A(16KB -> S_B1), B0(32KB)
    {
        const unsigned char* tsrc = (const unsigned char*)(g_tmp + (size_t)e0 * 16);
        for (int i = tid; i < 512; i += 256) cpa16(sb + S_TMP + i * 16, tsrc + i * 16);
        if (tid < 192) cpa16(sb + S_BL + tid * 16, (const unsigned char*)b2l + tid * 16);
        const unsigned char* ah = g_hh + (size_t)blockIdx.x * 16384;
        for (int i = tid; i < 1024; i += 256) cpa16(sb + S_B1 + i * 16, ah + i * 16);
        for (int i = tid; i < 2048; i += 256) cpa16(sb + S_B0 + i * 16, g_w2p + i * 16);
        CPA_COMMIT();
        CPA_WAIT0();
        __syncthreads();
    }

    // A fragments: rows wbase..wbase+15, 4 k-steps (from S_B1 staging)
    uint32_t aF[16];
    {
        uint32_t rowb = (uint32_t)(wbase + (lane & 15)) * 128 + ((lane >> 4) << 4);
#pragma unroll
        for (int s = 0; s < 4; ++s)
            ldsm_x4(&aF[4 * s], sb + S_B1 + sw128(rowb + 32 * s));
    }
    __syncthreads();   // all warps done reading A -> S_B1 reusable

    const int er0 = wbase + (lane >> 2);
    const int jq  = (lane & 3) * 2;
    float accA = 0.f, accB = 0.f;

#pragma unroll 1
    for (int ch = 0; ch < 6; ++ch) {
        const uint32_t bufC = (ch & 1) ? (sb + S_B1) : (sb + S_B0);
        // prefetch next chunk into the other buffer (overlapped with compute)
        if (ch < 5) {
            uint32_t bufN = (ch & 1) ? (sb + S_B0) : (sb + S_B1);
            const unsigned char* src = g_w2p + (size_t)(ch + 1) * 32768;
            for (int i = tid; i < 2048; i += 256) cpa16(bufN + i * 16, src + i * 16);
            CPA_COMMIT();
        }

#pragma unroll 2
        for (int nt = 0; nt < 16; ++nt) {
            const int nb = nt * 8;
            uint32_t bH[8], bL[8];
            uint32_t rb = (uint32_t)(nb + (lane & 7)) * 128 + ((lane >> 3) << 4);
#pragma unroll
            for (int p = 0; p < 2; ++p) {
                uint32_t off = sw128(rb + 64 * p);
                ldsm_x4(&bH[4 * p], bufC + off);
                ldsm_x4(&bL[4 * p], bufC + 16384 + off);
            }

            // 2 independent accumulation chains: h*W_hi and h*W_lo
            float c0[4] = {0,0,0,0}, c1[4] = {0,0,0,0};
#pragma unroll
            for (int s = 0; s < 4; ++s) {
                mma16816h(c0, &aF[4 * s], &bH[2 * s]);
                mma16816h(c1, &aF[4 * s], &bL[2 * s]);
            }

            const int g0 = ch * 128 + nb + jq;
            const int j0 = (nb & 8) + jq;
            float2 blv = *(float2*)&bl_s[g0];
            float2 t0 = *(float2*)&tmp_s[er0 * 16 + j0];
            float2 t1 = *(float2*)&tmp_s[(er0 + 8) * 16 + j0];
            accA += (c0[0] + c1[0] + blv.x) * t0.x + (c0[1] + c1[1] + blv.y) * t0.y;
            accB += (c0[2] + c1[2] + blv.x) * t1.x + (c0[3] + c1[3] + blv.y) * t1.y;

            if (nt & 1) {
                accA += __shfl_xor_sync(0xffffffffu, accA, 1);
                accA += __shfl_xor_sync(0xffffffffu, accA, 2);
                accB += __shfl_xor_sync(0xffffffffu, accB, 1);
                accB += __shfl_xor_sync(0xffffffffu, accB, 2);
                if ((lane & 3) == 0) {
                    int i = ch * 8 + (nt >> 1);
                    out_s[er0 * 49 + i]       = accA;
                    out_s[(er0 + 8) * 49 + i] = accB;
                }
                accA = 0.f; accB = 0.f;
            }
        }

        if (ch < 5) {
            CPA_WAIT0();
            __syncthreads();
        }
    }
    __syncthreads();

    // per-edge epilogue: qkv = out48.reshape(24,2) @ b2f -> scores + v
    if (tid < 128) {
        int e = e0 + tid;
        const float* o48 = out_s + tid * 49;
        float bb[8];
#pragma unroll
        for (int x = 0; x < 8; ++x) bb[x] = b2[(size_t)e * 8 + x];

#pragma unroll
        for (int h = 0; h < 4; ++h) {
            float s = 0.f;
#pragma unroll
            for (int mm = 0; mm < 2; ++mm) {
                int m = 2 * h + mm;
#pragma unroll
                for (int d = 0; d < 4; ++d) {
                    float q = o48[m * 2]       * bb[d] + o48[m * 2 + 1]       * bb[4 + d];
                    float k = o48[(8 + m) * 2] * bb[d] + o48[(8 + m) * 2 + 1] * bb[4 + d];
                    s = fmaf(q, k, s);
                }
            }
            g_sc[(size_t)e * 4 + h] = s * 0.35355339059327376f;
        }
#pragma unroll
        for (int m = 0; m < 8; ++m)
#pragma unroll
            for (int d = 0; d < 4; ++d)
                g_v[(size_t)e * 32 + m * 4 + d] =
                    o48[(16 + m) * 2] * bb[d] + o48[(16 + m) * 2 + 1] * bb[4 + d];
    }
}

// ---------------- kernel 3: softmax over K + weighted V + out-proj ----------
// one warp per node; coalesced g_v reads (4 x 128B per node).
__global__ void k3_attn(const float* __restrict__ Wout,
                        const float* __restrict__ bias,
                        float* __restrict__ out) {
    __shared__ float outsm[4][33];
    int tid = threadIdx.x;
    int warp = tid >> 5, lane = tid & 31;
    int n = blockIdx.x * 4 + warp;

    // scores: lane -> (k = lane>>1, head pair = lane&1)
    float2 sc2 = *reinterpret_cast<const float2*>(&g_sc[(size_t)n * 64 + lane * 2]);
    float s0 = sc2.x, s1 = sc2.y;

    float m0 = s0, m1 = s1;
#pragma unroll
    for (int off = 2; off < 32; off <<= 1) {
        m0 = fmaxf(m0, __shfl_xor_sync(0xffffffffu, m0, off));
        m1 = fmaxf(m1, __shfl_xor_sync(0xffffffffu, m1, off));
    }
    float e0v = expf(s0 - m0), e1v = expf(s1 - m1);
    float z0 = e0v, z1 = e1v;
#pragma unroll
    for (int off = 2; off < 32; off <<= 1) {
        z0 += __shfl_xor_sync(0xffffffffu, z0, off);
        z1 += __shfl_xor_sync(0xffffffffu, z1, off);
    }
    float a0 = e0v / z0, a1 = e1v / z1;   // attn[k=lane>>1][h = 2*(lane&1) + {0,1}]

    // v: coalesced. iteration it: lane holds v[n, k=it*4+(lane>>3), m=lane&7, d=0..3]
    const int m_mine = lane & 7;
    const int hsel   = (m_mine >> 1) & 1;          // h&1 for h = m>>1
    float r[4] = {0.f, 0.f, 0.f, 0.f};
#pragma unroll
    for (int it = 0; it < 4; ++it) {
        float4 vv = *reinterpret_cast<const float4*>(
            &g_v[(size_t)n * 512 + it * 128 + lane * 4]);
        // attn[k][h] lives at lane' = k*2 + (h>>1), component h&1
        int lsrc = 8 * it + ((lane >> 3) << 1) + ((lane >> 2) & 1);
        float av0 = __shfl_sync(0xffffffffu, a0, lsrc);
        float av1 = __shfl_sync(0xffffffffu, a1, lsrc);
        float a = hsel ? av1 : av0;
        r[0] = fmaf(a, vv.x, r[0]);
        r[1] = fmaf(a, vv.y, r[1]);
        r[2] = fmaf(a, vv.z, r[2]);
        r[3] = fmaf(a, vv.w, r[3]);
    }
    // reduce over k_local = lane>>3 (bits 3,4)
#pragma unroll
    for (int off = 8; off < 32; off <<= 1)
#pragma unroll
        for (int d = 0; d < 4; ++d)
            r[d] += __shfl_xor_sync(0xffffffffu, r[d], off);

    if (lane < 8) {
#pragma unroll
        for (int d = 0; d < 4; ++d)
            outsm[warp][m_mine * 4 + d] = r[d];
    }
    __syncwarp();

    // out-projection: d==0 uses W_out rows 0..7 (+bias), d>=1 uses rows 8..15
    int mm = lane >> 2, dd = lane & 3;
    int o = (dd == 0) ? mm : 8 + mm;
    float val = (dd == 0) ? bias[mm] : 0.f;
#pragma unroll
    for (int mp = 0; mp < 8; ++mp)
        val = fmaf(Wout[o * 8 + mp], outsm[warp][mp * 4 + dd], val);
    out[(size_t)n * 32 + lane] = val;
}

// ---------------- launcher ----------------------------------------------------
extern "C" void kernel_launch(void* const* d_in, const int* in_sizes, int n_in,
                              void* d_out, int out_size) {
    const float* b1   = (const float*)d_in[0];
    const float* b2   = (const float*)d_in[1];
    const float* ef   = (const float*)d_in[2];
    const float* f    = (const float*)d_in[3];
    const int*   nidx = (const int*)  d_in[4];
    const float* W1   = (const float*)d_in[5];
    const float* b1l  = (const float*)d_in[6];
    const float* W2   = (const float*)d_in[7];
    const float* b2l  = (const float*)d_in[8];
    const float* Wout = (const float*)d_in[9];
    const float* bias = (const float*)d_in[10];
    float* out = (float*)d_out;
    (void)in_sizes; (void)n_in; (void)out_size;

    cudaFuncSetAttribute(k2_mma, cudaFuncAttributeMaxDynamicSharedMemorySize, S_TOT);

    k0_w2prep<<<(768 * 64 + 255) / 256, 256>>>(W2);
    k1_prep<<<NEDGE / 64, 128>>>(ef, W1, b1l, f, nidx, b1);
    k2_mma<<<NTILES, 256, S_TOT>>>(b2, b2l);
    k3_attn<<<NNODES / 4, 128>>>(Wout, bias, out);
}

// round 6
// speedup vs baseline: 2.2665x; 1.0972x over previous
#include <cuda_runtime.h>
#include <cuda_fp16.h>
#include <math.h>
#include <stdint.h>

#define NNODES 10000
#define KNBR   16
#define NEDGE  (NNODES * KNBR)
#define NTILES (NEDGE / 128)          // 1250

// ---------------- scratch (static device globals; no allocation) ------------
__device__ __align__(16) unsigned char g_w2p[12 * 16384];   // W2 [chunk][hi/lo] fp16 SW128 tiles

// ---------------- helpers ----------------------------------------------------
__device__ __forceinline__ uint32_t sw128(uint32_t o) { return o ^ ((o >> 3) & 0x70u); }

__device__ __forceinline__ uint32_t smem_u32(const void* p) {
    uint32_t a;
    asm("{ .reg .u64 t; cvta.to.shared.u64 t, %1; cvt.u32.u64 %0, t; }" : "=r"(a) : "l"(p));
    return a;
}
__device__ __forceinline__ void ldsm_x4(uint32_t* r, uint32_t addr) {
    asm volatile("ldmatrix.sync.aligned.m8n8.x4.shared.b16 {%0,%1,%2,%3}, [%4];"
                 : "=r"(r[0]), "=r"(r[1]), "=r"(r[2]), "=r"(r[3]) : "r"(addr));
}
__device__ __forceinline__ void mma16816h(float* c, const uint32_t* a, const uint32_t* b) {
    asm volatile(
        "mma.sync.aligned.m16n8k16.row.col.f32.f16.f16.f32 "
        "{%0,%1,%2,%3}, {%4,%5,%6,%7}, {%8,%9}, {%0,%1,%2,%3};"
        : "+f"(c[0]), "+f"(c[1]), "+f"(c[2]), "+f"(c[3])
        : "r"(a[0]), "r"(a[1]), "r"(a[2]), "r"(a[3]), "r"(b[0]), "r"(b[1]));
}
__device__ __forceinline__ void cpa16(uint32_t dst, const void* src) {
    asm volatile("cp.async.cg.shared.global [%0], [%1], 16;" :: "r"(dst), "l"(src));
}
#define CPA_COMMIT() asm volatile("cp.async.commit_group;" ::: "memory")
#define CPA_WAIT0()  asm volatile("cp.async.wait_group 0;" ::: "memory")

// ---------------- kernel 0: W2 fp16 2-term split + pre-swizzle ---------------
__global__ void k0_w2prep(const float* __restrict__ W2) {
    int idx = blockIdx.x * 256 + threadIdx.x;
    if (idx >= 768 * 64) return;
    int r = idx >> 6, c = idx & 63;
    int ch = r >> 7, n = r & 127;
    float x = W2[idx];
    __half hi = __float2half_rn(x);
    __half lo = __float2half_rn(x - __half2float(hi));
    uint32_t off = sw128((uint32_t)(n * 128 + c * 2));
    *(__half*)(g_w2p + (size_t)(ch * 2 + 0) * 16384 + off) = hi;
    *(__half*)(g_w2p + (size_t)(ch * 2 + 1) * 16384 + off) = lo;
}

// ---------------- kernel 2: fully fused edge pipeline -------------------------
// prologue: MLP (h fp16 -> A tile) + tmp  | main: HMMA GEMM + j-contract
// epilogue: per-edge qkv -> per-node softmax/attention/out-proj (8 nodes/CTA)
#define S_TMP  0                    // 8192  (tmp 128x16 f32; outsm overlay later)
#define S_BL   8192                 // 3072
#define S_B0   11264                // 32768 (B buf0; sc_s/v_s overlay in epilogue)
#define S_B1   44032                // 32768 (A staged first, then B buf1)
#define S_OUT  76800                // 25088 (W1s overlay in prologue; out 128x49)
#define S_TOT  101888

#define SV_SC  (S_B0)               // sc_s: 128*4 f32 = 2048
#define SV_V   (S_B0 + 2048)        // v_s: 128*32 f32 = 16384

__global__ void __launch_bounds__(256, 2)
k2_fused(const float* __restrict__ ef,
         const float* __restrict__ W1,
         const float* __restrict__ b1lin,
         const float* __restrict__ f,
         const int*   __restrict__ nidx,
         const float* __restrict__ b1,
         const float* __restrict__ b2,
         const float* __restrict__ b2l,
         const float* __restrict__ Wout,
         const float* __restrict__ bias,
         float* __restrict__ out) {
    extern __shared__ __align__(1024) unsigned char smem[];
    const uint32_t sb = smem_u32(smem);
    float* tmp_s = (float*)(smem + S_TMP);
    float* bl_s  = (float*)(smem + S_BL);
    float* out_s = (float*)(smem + S_OUT);
    float* W1s   = (float*)(smem + S_OUT);   // prologue overlay (2112 floats)

    const int tid = threadIdx.x, wid = tid >> 5, lane = tid & 31;
    const int e0 = blockIdx.x << 7;
    const int wbase = wid * 16;

    // ---- async staging: bl (3KB) + B chunk0 (32KB); W1 -> smem (padded) ----
    if (tid < 192) cpa16(sb + S_BL + tid * 16, (const unsigned char*)b2l + tid * 16);
    for (int i = tid; i < 2048; i += 256) cpa16(sb + S_B0 + i * 16, g_w2p + i * 16);
    CPA_COMMIT();
    for (int idx = tid; idx < 2048; idx += 256)
        W1s[(idx >> 5) * 33 + (idx & 31)] = W1[idx];
    __syncthreads();

    // ---- fused k1: h = gelu(W1 ef + b) -> fp16 swizzled A tile; tmp -> smem ----
    {
        float blv0 = b1lin[lane], blv1 = b1lin[lane + 32];
        for (int it = 0; it < 16; ++it) {
            int erow = wbase + it;
            int e = e0 + erow;
            float efr = ef[(size_t)e * 32 + lane];
            float a0 = blv0, a1 = blv1;
#pragma unroll
            for (int d = 0; d < 32; ++d) {
                float ed = __shfl_sync(0xffffffffu, efr, d);
                a0 = fmaf(W1s[lane * 33 + d], ed, a0);
                a1 = fmaf(W1s[(lane + 32) * 33 + d], ed, a1);
            }
            a0 = a0 * 0.5f * (1.0f + erff(a0 * 0.70710678118654752f));
            a1 = a1 * 0.5f * (1.0f + erff(a1 * 0.70710678118654752f));

            *(__half*)(smem + S_B1 + sw128((uint32_t)(erow * 128 + lane * 2)))        = __float2half_rn(a0);
            *(__half*)(smem + S_B1 + sw128((uint32_t)(erow * 128 + (lane + 32) * 2))) = __float2half_rn(a1);

            if (lane < 16) {
                int m = lane >> 1, l = lane & 1;
                int nbr = nidx[e];
                const float* frow = f + (size_t)nbr * 32 + m * 4;
                const float* brow = b1 + (size_t)e * 8;
                float t = 0.f;
#pragma unroll
                for (int d = 0; d < 4; ++d)
                    t = fmaf(frow[d], brow[d * 2 + l], t);
                tmp_s[erow * 16 + lane] = t;
            }
        }
    }
    __syncthreads();   // A tile + tmp complete (also: W1s reads done -> out_s free)

    // ---- A fragments: rows wbase..wbase+15, 4 k-steps ----
    uint32_t aF[16];
    {
        uint32_t rowb = (uint32_t)(wbase + (lane & 15)) * 128 + ((lane >> 4) << 4);
#pragma unroll
        for (int s = 0; s < 4; ++s)
            ldsm_x4(&aF[4 * s], sb + S_B1 + sw128(rowb + 32 * s));
    }
    CPA_WAIT0();       // B0 + bl arrived
    __syncthreads();   // all warps done reading A -> S_B1 reusable as B buf

    const int er0 = wbase + (lane >> 2);
    const int jq  = (lane & 3) * 2;
    float accA = 0.f, accB = 0.f;

#pragma unroll 1
    for (int ch = 0; ch < 6; ++ch) {
        const uint32_t bufC = (ch & 1) ? (sb + S_B1) : (sb + S_B0);
        if (ch < 5) {
            uint32_t bufN = (ch & 1) ? (sb + S_B0) : (sb + S_B1);
            const unsigned char* src = g_w2p + (size_t)(ch + 1) * 32768;
            for (int i = tid; i < 2048; i += 256) cpa16(bufN + i * 16, src + i * 16);
            CPA_COMMIT();
        }

#pragma unroll 2
        for (int nt = 0; nt < 16; ++nt) {
            const int nb = nt * 8;
            uint32_t bH[8], bL[8];
            uint32_t rb = (uint32_t)(nb + (lane & 7)) * 128 + ((lane >> 3) << 4);
#pragma unroll
            for (int p = 0; p < 2; ++p) {
                uint32_t off = sw128(rb + 64 * p);
                ldsm_x4(&bH[4 * p], bufC + off);
                ldsm_x4(&bL[4 * p], bufC + 16384 + off);
            }

            float c0[4] = {0,0,0,0}, c1[4] = {0,0,0,0};
#pragma unroll
            for (int s = 0; s < 4; ++s) {
                mma16816h(c0, &aF[4 * s], &bH[2 * s]);
                mma16816h(c1, &aF[4 * s], &bL[2 * s]);
            }

            const int g0 = ch * 128 + nb + jq;
            const int j0 = (nb & 8) + jq;
            float2 blv = *(float2*)&bl_s[g0];
            float2 t0 = *(float2*)&tmp_s[er0 * 16 + j0];
            float2 t1 = *(float2*)&tmp_s[(er0 + 8) * 16 + j0];
            accA += (c0[0] + c1[0] + blv.x) * t0.x + (c0[1] + c1[1] + blv.y) * t0.y;
            accB += (c0[2] + c1[2] + blv.x) * t1.x + (c0[3] + c1[3] + blv.y) * t1.y;

            if (nt & 1) {
                accA += __shfl_xor_sync(0xffffffffu, accA, 1);
                accA += __shfl_xor_sync(0xffffffffu, accA, 2);
                accB += __shfl_xor_sync(0xffffffffu, accB, 1);
                accB += __shfl_xor_sync(0xffffffffu, accB, 2);
                if ((lane & 3) == 0) {
                    int i = ch * 8 + (nt >> 1);
                    out_s[er0 * 49 + i]       = accA;
                    out_s[(er0 + 8) * 49 + i] = accB;
                }
                accA = 0.f; accB = 0.f;
            }
        }

        if (ch < 5) {
            CPA_WAIT0();
            __syncthreads();
        }
    }
    __syncthreads();   // out_s complete; B buffers dead -> sc_s/v_s overlay

    // ---- per-edge: qkv = out48.reshape(24,2) @ b2f -> scores + v (to smem) ----
    float* sc_s = (float*)(smem + SV_SC);
    float* v_s  = (float*)(smem + SV_V);
    if (tid < 128) {
        int e = e0 + tid;
        const float* o48 = out_s + tid * 49;
        float bb[8];
#pragma unroll
        for (int x = 0; x < 8; ++x) bb[x] = b2[(size_t)e * 8 + x];

#pragma unroll
        for (int h = 0; h < 4; ++h) {
            float s = 0.f;
#pragma unroll
            for (int mm = 0; mm < 2; ++mm) {
                int m = 2 * h + mm;
#pragma unroll
                for (int d = 0; d < 4; ++d) {
                    float q = o48[m * 2]       * bb[d] + o48[m * 2 + 1]       * bb[4 + d];
                    float k = o48[(8 + m) * 2] * bb[d] + o48[(8 + m) * 2 + 1] * bb[4 + d];
                    s = fmaf(q, k, s);
                }
            }
            sc_s[tid * 4 + h] = s * 0.35355339059327376f;
        }
#pragma unroll
        for (int m = 0; m < 8; ++m)
#pragma unroll
            for (int d = 0; d < 4; ++d)
                v_s[tid * 32 + m * 4 + d] =
                    o48[(16 + m) * 2] * bb[d] + o48[(16 + m) * 2 + 1] * bb[4 + d];
    }
    __syncthreads();

    // ---- per-node attention: warp wid handles node blockIdx.x*8 + wid ----
    {
        float* outsm = (float*)(smem + S_TMP) + wid * 33;   // overlay on tmp_s
        int n = blockIdx.x * 8 + wid;
        int nb = wid * 16;   // node's first local edge

        float2 sc2 = *(float2*)&sc_s[nb * 4 + lane * 2];
        float s0 = sc2.x, s1 = sc2.y;

        float m0 = s0, m1 = s1;
#pragma unroll
        for (int off = 2; off < 32; off <<= 1) {
            m0 = fmaxf(m0, __shfl_xor_sync(0xffffffffu, m0, off));
            m1 = fmaxf(m1, __shfl_xor_sync(0xffffffffu, m1, off));
        }
        float e0v = expf(s0 - m0), e1v = expf(s1 - m1);
        float z0 = e0v, z1 = e1v;
#pragma unroll
        for (int off = 2; off < 32; off <<= 1) {
            z0 += __shfl_xor_sync(0xffffffffu, z0, off);
            z1 += __shfl_xor_sync(0xffffffffu, z1, off);
        }
        float a0 = e0v / z0, a1 = e1v / z1;

        const int m_mine = lane & 7;
        const int hsel   = (m_mine >> 1) & 1;
        float r[4] = {0.f, 0.f, 0.f, 0.f};
#pragma unroll
        for (int it = 0; it < 4; ++it) {
            float4 vv = *(float4*)&v_s[nb * 32 + it * 128 + lane * 4];
            int lsrc = 8 * it + ((lane >> 3) << 1) + ((lane >> 2) & 1);
            float av0 = __shfl_sync(0xffffffffu, a0, lsrc);
            float av1 = __shfl_sync(0xffffffffu, a1, lsrc);
            float a = hsel ? av1 : av0;
            r[0] = fmaf(a, vv.x, r[0]);
            r[1] = fmaf(a, vv.y, r[1]);
            r[2] = fmaf(a, vv.z, r[2]);
            r[3] = fmaf(a, vv.w, r[3]);
        }
#pragma unroll
        for (int off = 8; off < 32; off <<= 1)
#pragma unroll
            for (int d = 0; d < 4; ++d)
                r[d] += __shfl_xor_sync(0xffffffffu, r[d], off);

        if (lane < 8) {
#pragma unroll
            for (int d = 0; d < 4; ++d)
                outsm[m_mine * 4 + d] = r[d];
        }
        __syncwarp();

        int mm = lane >> 2, dd = lane & 3;
        int o = (dd == 0) ? mm : 8 + mm;
        float val = (dd == 0) ? bias[mm] : 0.f;
#pragma unroll
        for (int mp = 0; mp < 8; ++mp)
            val = fmaf(Wout[o * 8 + mp], outsm[mp * 4 + dd], val);
        out[(size_t)n * 32 + lane] = val;
    }
}

// ---------------- launcher ----------------------------------------------------
extern "C" void kernel_launch(void* const* d_in, const int* in_sizes, int n_in,
                              void* d_out, int out_size) {
    const float* b1   = (const float*)d_in[0];
    const float* b2   = (const float*)d_in[1];
    const float* ef   = (const float*)d_in[2];
    const float* f    = (const float*)d_in[3];
    const int*   nidx = (const int*)  d_in[4];
    const float* W1   = (const float*)d_in[5];
    const float* b1l  = (const float*)d_in[6];
    const float* W2   = (const float*)d_in[7];
    const float* b2l  = (const float*)d_in[8];
    const float* Wout = (const float*)d_in[9];
    const float* bias = (const float*)d_in[10];
    float* out = (float*)d_out;
    (void)in_sizes; (void)n_in; (void)out_size;

    cudaFuncSetAttribute(k2_fused, cudaFuncAttributeMaxDynamicSharedMemorySize, S_TOT);

    k0_w2prep<<<(768 * 64 + 255) / 256, 256>>>(W2);
    k2_fused<<<NTILES, 256, S_TOT>>>(ef, W1, b1l, f, nidx, b1, b2, b2l, Wout, bias, out);
}

// round 7
// speedup vs baseline: 2.6390x; 1.1644x over previous
#include <cuda_runtime.h>
#include <cuda_fp16.h>
#include <math.h>
#include <stdint.h>

#define NNODES 10000
#define KNBR   16
#define NEDGE  (NNODES * KNBR)
#define NTILES (NEDGE / 128)          // 1250

// ---------------- scratch (static device globals; no allocation) ------------
__device__ __align__(16) unsigned char g_w2p[12 * 16384];   // W2 [chunk][hi/lo] fp16 SW128 tiles

// ---------------- helpers ----------------------------------------------------
__device__ __forceinline__ uint32_t sw128(uint32_t o) { return o ^ ((o >> 3) & 0x70u); }

__device__ __forceinline__ uint32_t smem_u32(const void* p) {
    uint32_t a;
    asm("{ .reg .u64 t; cvta.to.shared.u64 t, %1; cvt.u32.u64 %0, t; }" : "=r"(a) : "l"(p));
    return a;
}
__device__ __forceinline__ void ldsm_x4(uint32_t* r, uint32_t addr) {
    asm volatile("ldmatrix.sync.aligned.m8n8.x4.shared.b16 {%0,%1,%2,%3}, [%4];"
                 : "=r"(r[0]), "=r"(r[1]), "=r"(r[2]), "=r"(r[3]) : "r"(addr));
}
__device__ __forceinline__ void mma16816h(float* c, const uint32_t* a, const uint32_t* b) {
    asm volatile(
        "mma.sync.aligned.m16n8k16.row.col.f32.f16.f16.f32 "
        "{%0,%1,%2,%3}, {%4,%5,%6,%7}, {%8,%9}, {%0,%1,%2,%3};"
        : "+f"(c[0]), "+f"(c[1]), "+f"(c[2]), "+f"(c[3])
        : "r"(a[0]), "r"(a[1]), "r"(a[2]), "r"(a[3]), "r"(b[0]), "r"(b[1]));
}
__device__ __forceinline__ void cpa16(uint32_t dst, const void* src) {
    asm volatile("cp.async.cg.shared.global [%0], [%1], 16;" :: "r"(dst), "l"(src));
}
#define CPA_COMMIT() asm volatile("cp.async.commit_group;" ::: "memory")
#define CPA_WAIT0()  asm volatile("cp.async.wait_group 0;" ::: "memory")

// ---------------- kernel 0: W2 fp16 2-term split + pre-swizzle ---------------
__global__ void k0_w2prep(const float* __restrict__ W2) {
    int idx = blockIdx.x * 256 + threadIdx.x;
    if (idx >= 768 * 64) return;
    int r = idx >> 6, c = idx & 63;
    int ch = r >> 7, n = r & 127;
    float x = W2[idx];
    __half hi = __float2half_rn(x);
    __half lo = __float2half_rn(x - __half2float(hi));
    uint32_t off = sw128((uint32_t)(n * 128 + c * 2));
    *(__half*)(g_w2p + (size_t)(ch * 2 + 0) * 16384 + off) = hi;
    *(__half*)(g_w2p + (size_t)(ch * 2 + 1) * 16384 + off) = lo;
}

// ---------------- kernel 2: fully fused edge pipeline -------------------------
// prologue: MLP (h fp16 -> A tile) + tmp  | main: HMMA GEMM (warp tile M=32,N=64)
// epilogue: per-edge qkv -> per-node softmax/attention/out-proj (8 nodes/CTA)
#define S_TMP  0                    // 8192  (tmp 128x16 f32; outsm overlay later)
#define S_BL   8192                 // 3072
#define S_B0   11264                // 32768 (B buf0; sc_s/v_s overlay in epilogue)
#define S_B1   44032                // 32768 (A staged first, then B buf1)
#define S_OUT  76800                // 25088 (W1s overlay in prologue; out 128x49)
#define S_TOT  101888

#define SV_SC  (S_B0)               // sc_s: 128*4 f32 = 2048
#define SV_V   (S_B0 + 2048)        // v_s: 128*32 f32 = 16384

__global__ void __launch_bounds__(256, 2)
k2_fused(const float* __restrict__ ef,
         const float* __restrict__ W1,
         const float* __restrict__ b1lin,
         const float* __restrict__ f,
         const int*   __restrict__ nidx,
         const float* __restrict__ b1,
         const float* __restrict__ b2,
         const float* __restrict__ b2l,
         const float* __restrict__ Wout,
         const float* __restrict__ bias,
         float* __restrict__ out) {
    extern __shared__ __align__(1024) unsigned char smem[];
    const uint32_t sb = smem_u32(smem);
    float* tmp_s = (float*)(smem + S_TMP);
    float* bl_s  = (float*)(smem + S_BL);
    float* out_s = (float*)(smem + S_OUT);
    float* W1s   = (float*)(smem + S_OUT);   // prologue overlay (2112 floats)

    const int tid = threadIdx.x, wid = tid >> 5, lane = tid & 31;
    const int e0 = blockIdx.x << 7;

    // ---- async staging: bl (3KB) + B chunk0 (32KB); W1 -> smem (padded) ----
    if (tid < 192) cpa16(sb + S_BL + tid * 16, (const unsigned char*)b2l + tid * 16);
    for (int i = tid; i < 2048; i += 256) cpa16(sb + S_B0 + i * 16, g_w2p + i * 16);
    CPA_COMMIT();
    for (int idx = tid; idx < 2048; idx += 256)
        W1s[(idx >> 5) * 33 + (idx & 31)] = W1[idx];
    __syncthreads();

    // ---- fused k1: h = gelu(W1 ef + b) -> fp16 swizzled A tile; tmp -> smem ----
    {
        const int pbase = wid * 16;   // prologue edge mapping (independent)
        float blv0 = b1lin[lane], blv1 = b1lin[lane + 32];
        for (int it = 0; it < 16; ++it) {
            int erow = pbase + it;
            int e = e0 + erow;
            float efr = ef[(size_t)e * 32 + lane];
            float a0 = blv0, a1 = blv1;
#pragma unroll
            for (int d = 0; d < 32; ++d) {
                float ed = __shfl_sync(0xffffffffu, efr, d);
                a0 = fmaf(W1s[lane * 33 + d], ed, a0);
                a1 = fmaf(W1s[(lane + 32) * 33 + d], ed, a1);
            }
            a0 = a0 * 0.5f * (1.0f + erff(a0 * 0.70710678118654752f));
            a1 = a1 * 0.5f * (1.0f + erff(a1 * 0.70710678118654752f));

            *(__half*)(smem + S_B1 + sw128((uint32_t)(erow * 128 + lane * 2)))        = __float2half_rn(a0);
            *(__half*)(smem + S_B1 + sw128((uint32_t)(erow * 128 + (lane + 32) * 2))) = __float2half_rn(a1);

            if (lane < 16) {
                int m = lane >> 1, l = lane & 1;
                int nbr = nidx[e];
                const float* frow = f + (size_t)nbr * 32 + m * 4;
                const float* brow = b1 + (size_t)e * 8;
                float t = 0.f;
#pragma unroll
                for (int d = 0; d < 4; ++d)
                    t = fmaf(frow[d], brow[d * 2 + l], t);
                tmp_s[erow * 16 + lane] = t;
            }
        }
    }
    __syncthreads();   // A tile + tmp complete (W1s reads done -> out_s free)

    // ---- GEMM warp tiling: wn = n-half (0/1), wm = m-quarter (0..3) ----
    const int wn = wid >> 2, wm = wid & 3;

    // A fragments: rows wm*32..wm*32+31 (2 m-tiles), 4 k-steps
    uint32_t aF[32];
    {
#pragma unroll
        for (int t = 0; t < 2; ++t) {
            uint32_t rowb = (uint32_t)(wm * 32 + t * 16 + (lane & 15)) * 128 + ((lane >> 4) << 4);
#pragma unroll
            for (int s = 0; s < 4; ++s)
                ldsm_x4(&aF[t * 16 + 4 * s], sb + S_B1 + sw128(rowb + 32 * s));
        }
    }
    CPA_WAIT0();       // B0 + bl arrived
    __syncthreads();   // all warps done reading A -> S_B1 reusable as B buf

    const int er0 = wm * 32 + (lane >> 2);
    const int jq  = (lane & 3) * 2;
    float acc0 = 0.f, acc1 = 0.f, acc2 = 0.f, acc3 = 0.f;

#pragma unroll 1
    for (int ch = 0; ch < 6; ++ch) {
        const uint32_t bufC = (ch & 1) ? (sb + S_B1) : (sb + S_B0);
        if (ch < 5) {
            uint32_t bufN = (ch & 1) ? (sb + S_B0) : (sb + S_B1);
            const unsigned char* src = g_w2p + (size_t)(ch + 1) * 32768;
            for (int i = tid; i < 2048; i += 256) cpa16(bufN + i * 16, src + i * 16);
            CPA_COMMIT();
        }

#pragma unroll 2
        for (int nt = 0; nt < 8; ++nt) {
            const int nb = wn * 64 + nt * 8;    // col base within chunk
            uint32_t bH[8], bL[8];
            uint32_t rb = (uint32_t)(nb + (lane & 7)) * 128 + ((lane >> 3) << 4);
#pragma unroll
            for (int p = 0; p < 2; ++p) {
                uint32_t off = sw128(rb + 64 * p);
                ldsm_x4(&bH[4 * p], bufC + off);
                ldsm_x4(&bL[4 * p], bufC + 16384 + off);
            }

            // 4 independent chains: (m-tile 0/1) x (hi/lo)
            float cH0[4] = {0,0,0,0}, cL0[4] = {0,0,0,0};
            float cH1[4] = {0,0,0,0}, cL1[4] = {0,0,0,0};
#pragma unroll
            for (int s = 0; s < 4; ++s) {
                mma16816h(cH0, &aF[4 * s],      &bH[2 * s]);
                mma16816h(cL0, &aF[4 * s],      &bL[2 * s]);
                mma16816h(cH1, &aF[16 + 4 * s], &bH[2 * s]);
                mma16816h(cL1, &aF[16 + 4 * s], &bL[2 * s]);
            }

            const int g0 = ch * 128 + nb + jq;
            const int j0 = ((nt & 1) << 3) + jq;
            float2 blv = *(float2*)&bl_s[g0];
            float2 t0 = *(float2*)&tmp_s[er0 * 16 + j0];
            float2 t1 = *(float2*)&tmp_s[(er0 + 8) * 16 + j0];
            float2 t2 = *(float2*)&tmp_s[(er0 + 16) * 16 + j0];
            float2 t3 = *(float2*)&tmp_s[(er0 + 24) * 16 + j0];
            acc0 += (cH0[0] + cL0[0] + blv.x) * t0.x + (cH0[1] + cL0[1] + blv.y) * t0.y;
            acc1 += (cH0[2] + cL0[2] + blv.x) * t1.x + (cH0[3] + cL0[3] + blv.y) * t1.y;
            acc2 += (cH1[0] + cL1[0] + blv.x) * t2.x + (cH1[1] + cL1[1] + blv.y) * t2.y;
            acc3 += (cH1[2] + cL1[2] + blv.x) * t3.x + (cH1[3] + cL1[3] + blv.y) * t3.y;

            if (nt & 1) {
                acc0 += __shfl_xor_sync(0xffffffffu, acc0, 1);
                acc0 += __shfl_xor_sync(0xffffffffu, acc0, 2);
                acc1 += __shfl_xor_sync(0xffffffffu, acc1, 1);
                acc1 += __shfl_xor_sync(0xffffffffu, acc1, 2);
                acc2 += __shfl_xor_sync(0xffffffffu, acc2, 1);
                acc2 += __shfl_xor_sync(0xffffffffu, acc2, 2);
                acc3 += __shfl_xor_sync(0xffffffffu, acc3, 1);
                acc3 += __shfl_xor_sync(0xffffffffu, acc3, 2);
                if ((lane & 3) == 0) {
                    int i = ch * 8 + wn * 4 + (nt >> 1);
                    out_s[er0 * 49 + i]        = acc0;
                    out_s[(er0 + 8) * 49 + i]  = acc1;
                    out_s[(er0 + 16) * 49 + i] = acc2;
                    out_s[(er0 + 24) * 49 + i] = acc3;
                }
                acc0 = 0.f; acc1 = 0.f; acc2 = 0.f; acc3 = 0.f;
            }
        }

        if (ch < 5) {
            CPA_WAIT0();
            __syncthreads();
        }
    }
    __syncthreads();   // out_s complete; B buffers dead -> sc_s/v_s overlay

    // ---- per-edge: qkv = out48.reshape(24,2) @ b2f -> scores + v (to smem) ----
    float* sc_s = (float*)(smem + SV_SC);
    float* v_s  = (float*)(smem + SV_V);
    if (tid < 128) {
        int e = e0 + tid;
        const float* o48 = out_s + tid * 49;
        float bb[8];
#pragma unroll
        for (int x = 0; x < 8; ++x) bb[x] = b2[(size_t)e * 8 + x];

#pragma unroll
        for (int h = 0; h < 4; ++h) {
            float s = 0.f;
#pragma unroll
            for (int mm = 0; mm < 2; ++mm) {
                int m = 2 * h + mm;
#pragma unroll
                for (int d = 0; d < 4; ++d) {
                    float q = o48[m * 2]       * bb[d] + o48[m * 2 + 1]       * bb[4 + d];
                    float k = o48[(8 + m) * 2] * bb[d] + o48[(8 + m) * 2 + 1] * bb[4 + d];
                    s = fmaf(q, k, s);
                }
            }
            sc_s[tid * 4 + h] = s * 0.35355339059327376f;
        }
#pragma unroll
        for (int m = 0; m < 8; ++m)
#pragma unroll
            for (int d = 0; d < 4; ++d)
                v_s[tid * 32 + m * 4 + d] =
                    o48[(16 + m) * 2] * bb[d] + o48[(16 + m) * 2 + 1] * bb[4 + d];
    }
    __syncthreads();

    // ---- per-node attention: warp wid handles node blockIdx.x*8 + wid ----
    {
        float* outsm = (float*)(smem + S_TMP) + wid * 33;   // overlay on tmp_s
        int n = blockIdx.x * 8 + wid;
        int nb = wid * 16;   // node's first local edge

        float2 sc2 = *(float2*)&sc_s[nb * 4 + lane * 2];
        float s0 = sc2.x, s1 = sc2.y;

        float m0 = s0, m1 = s1;
#pragma unroll
        for (int off = 2; off < 32; off <<= 1) {
            m0 = fmaxf(m0, __shfl_xor_sync(0xffffffffu, m0, off));
            m1 = fmaxf(m1, __shfl_xor_sync(0xffffffffu, m1, off));
        }
        float e0v = expf(s0 - m0), e1v = expf(s1 - m1);
        float z0 = e0v, z1 = e1v;
#pragma unroll
        for (int off = 2; off < 32; off <<= 1) {
            z0 += __shfl_xor_sync(0xffffffffu, z0, off);
            z1 += __shfl_xor_sync(0xffffffffu, z1, off);
        }
        float a0 = e0v / z0, a1 = e1v / z1;

        const int m_mine = lane & 7;
        const int hsel   = (m_mine >> 1) & 1;
        float r[4] = {0.f, 0.f, 0.f, 0.f};
#pragma unroll
        for (int it = 0; it < 4; ++it) {
            float4 vv = *(float4*)&v_s[nb * 32 + it * 128 + lane * 4];
            int lsrc = 8 * it + ((lane >> 3) << 1) + ((lane >> 2) & 1);
            float av0 = __shfl_sync(0xffffffffu, a0, lsrc);
            float av1 = __shfl_sync(0xffffffffu, a1, lsrc);
            float a = hsel ? av1 : av0;
            r[0] = fmaf(a, vv.x, r[0]);
            r[1] = fmaf(a, vv.y, r[1]);
            r[2] = fmaf(a, vv.z, r[2]);
            r[3] = fmaf(a, vv.w, r[3]);
        }
#pragma unroll
        for (int off = 8; off < 32; off <<= 1)
#pragma unroll
            for (int d = 0; d < 4; ++d)
                r[d] += __shfl_xor_sync(0xffffffffu, r[d], off);

        if (lane < 8) {
#pragma unroll
            for (int d = 0; d < 4; ++d)
                outsm[m_mine * 4 + d] = r[d];
        }
        __syncwarp();

        int mm = lane >> 2, dd = lane & 3;
        int o = (dd == 0) ? mm : 8 + mm;
        float val = (dd == 0) ? bias[mm] : 0.f;
#pragma unroll
        for (int mp = 0; mp < 8; ++mp)
            val = fmaf(Wout[o * 8 + mp], outsm[mp * 4 + dd], val);
        out[(size_t)n * 32 + lane] = val;
    }
}

// ---------------- launcher ----------------------------------------------------
extern "C" void kernel_launch(void* const* d_in, const int* in_sizes, int n_in,
                              void* d_out, int out_size) {
    const float* b1   = (const float*)d_in[0];
    const float* b2   = (const float*)d_in[1];
    const float* ef   = (const float*)d_in[2];
    const float* f    = (const float*)d_in[3];
    const int*   nidx = (const int*)  d_in[4];
    const float* W1   = (const float*)d_in[5];
    const float* b1l  = (const float*)d_in[6];
    const float* W2   = (const float*)d_in[7];
    const float* b2l  = (const float*)d_in[8];
    const float* Wout = (const float*)d_in[9];
    const float* bias = (const float*)d_in[10];
    float* out = (float*)d_out;
    (void)in_sizes; (void)n_in; (void)out_size;

    cudaFuncSetAttribute(k2_fused, cudaFuncAttributeMaxDynamicSharedMemorySize, S_TOT);

    k0_w2prep<<<(768 * 64 + 255) / 256, 256>>>(W2);
    k2_fused<<<NTILES, 256, S_TOT>>>(ef, W1, b1l, f, nidx, b1, b2, b2l, Wout, bias, out);
}

// round 8
// speedup vs baseline: 3.3954x; 1.2866x over previous
#include <cuda_runtime.h>
#include <cuda_fp16.h>
#include <math.h>
#include <stdint.h>

#define NNODES 10000
#define KNBR   16
#define NEDGE  (NNODES * KNBR)
#define NTILES (NEDGE / 128)          // 1250

// ---------------- scratch (static device globals; no allocation) ------------
__device__ __align__(16) unsigned char g_w2p[12 * 16384];   // W2 [chunk][hi/lo] fp16 SW128 tiles

// ---------------- helpers ----------------------------------------------------
__device__ __forceinline__ uint32_t sw128(uint32_t o) { return o ^ ((o >> 3) & 0x70u); }

__device__ __forceinline__ uint32_t smem_u32(const void* p) {
    uint32_t a;
    asm("{ .reg .u64 t; cvta.to.shared.u64 t, %1; cvt.u32.u64 %0, t; }" : "=r"(a) : "l"(p));
    return a;
}
__device__ __forceinline__ void ldsm_x4(uint32_t* r, uint32_t addr) {
    asm volatile("ldmatrix.sync.aligned.m8n8.x4.shared.b16 {%0,%1,%2,%3}, [%4];"
                 : "=r"(r[0]), "=r"(r[1]), "=r"(r[2]), "=r"(r[3]) : "r"(addr));
}
__device__ __forceinline__ void mma16816h(float* c, const uint32_t* a, const uint32_t* b) {
    asm volatile(
        "mma.sync.aligned.m16n8k16.row.col.f32.f16.f16.f32 "
        "{%0,%1,%2,%3}, {%4,%5,%6,%7}, {%8,%9}, {%0,%1,%2,%3};"
        : "+f"(c[0]), "+f"(c[1]), "+f"(c[2]), "+f"(c[3])
        : "r"(a[0]), "r"(a[1]), "r"(a[2]), "r"(a[3]), "r"(b[0]), "r"(b[1]));
}
__device__ __forceinline__ void cpa16(uint32_t dst, const void* src) {
    asm volatile("cp.async.cg.shared.global [%0], [%1], 16;" :: "r"(dst), "l"(src));
}
#define CPA_COMMIT() asm volatile("cp.async.commit_group;" ::: "memory")
#define CPA_WAIT0()  asm volatile("cp.async.wait_group 0;" ::: "memory")

// ---------------- kernel 0: W2 fp16 2-term split + pre-swizzle ---------------
__global__ void k0_w2prep(const float* __restrict__ W2) {
    int idx = blockIdx.x * 256 + threadIdx.x;
    if (idx >= 768 * 64) return;
    int r = idx >> 6, c = idx & 63;
    int ch = r >> 7, n = r & 127;
    float x = W2[idx];
    __half hi = __float2half_rn(x);
    __half lo = __float2half_rn(x - __half2float(hi));
    uint32_t off = sw128((uint32_t)(n * 128 + c * 2));
    *(__half*)(g_w2p + (size_t)(ch * 2 + 0) * 16384 + off) = hi;
    *(__half*)(g_w2p + (size_t)(ch * 2 + 1) * 16384 + off) = lo;
}

// ---------------- kernel 2: fully fused edge pipeline -------------------------
#define S_TMP  0                    // 8192  (tmp 128x16 f32; outsm overlay later)
#define S_BL   8192                 // 3072
#define S_B0   11264                // 32768 (B buf0; sc_s/v_s overlay in epilogue)
#define S_B1   44032                // 32768 (A staged first, then B buf1)
#define S_OUT  76800                // 25088 (W1s overlay in prologue; out 128x49)
#define S_TOT  101888

#define SV_SC  (S_B0)               // sc_s: 128*4 f32 = 2048
#define SV_V   (S_B0 + 2048)        // v_s: 128*32 f32 = 16384

__global__ void __launch_bounds__(256, 2)
k2_fused(const float* __restrict__ ef,
         const float* __restrict__ W1,
         const float* __restrict__ b1lin,
         const float* __restrict__ f,
         const int*   __restrict__ nidx,
         const float* __restrict__ b1,
         const float* __restrict__ b2,
         const float* __restrict__ b2l,
         const float* __restrict__ Wout,
         const float* __restrict__ bias,
         float* __restrict__ out) {
    extern __shared__ __align__(1024) unsigned char smem[];
    const uint32_t sb = smem_u32(smem);
    float* tmp_s = (float*)(smem + S_TMP);
    float* bl_s  = (float*)(smem + S_BL);
    float* out_s = (float*)(smem + S_OUT);
    float* W1s   = (float*)(smem + S_OUT);   // prologue overlay (2112 floats)

    const int tid = threadIdx.x, wid = tid >> 5, lane = tid & 31;
    const int e0 = blockIdx.x << 7;

    // ---- async staging: bl (3KB) + B chunk0 (32KB); W1 -> smem (padded) ----
    if (tid < 192) cpa16(sb + S_BL + tid * 16, (const unsigned char*)b2l + tid * 16);
    for (int i = tid; i < 2048; i += 256) cpa16(sb + S_B0 + i * 16, g_w2p + i * 16);
    CPA_COMMIT();
    for (int idx = tid; idx < 2048; idx += 256)
        W1s[(idx >> 5) * 33 + (idx & 31)] = W1[idx];
    __syncthreads();

    // ---- fused k1 (d-outer, 8 edges/pass): h -> fp16 swizzled A tile --------
    {
        const int pbase = wid * 16;
        float blv0 = b1lin[lane], blv1 = b1lin[lane + 32];
#pragma unroll
        for (int pass = 0; pass < 2; ++pass) {
            const int eb = pbase + pass * 8;
            float efr[8], a0[8], a1[8];
#pragma unroll
            for (int q = 0; q < 8; ++q) {
                efr[q] = ef[(size_t)(e0 + eb + q) * 32 + lane];
                a0[q] = blv0; a1[q] = blv1;
            }
#pragma unroll
            for (int d = 0; d < 32; ++d) {
                float w0 = W1s[lane * 33 + d];
                float w1 = W1s[(lane + 32) * 33 + d];
#pragma unroll
                for (int q = 0; q < 8; ++q) {
                    float ed = __shfl_sync(0xffffffffu, efr[q], d);
                    a0[q] = fmaf(w0, ed, a0[q]);
                    a1[q] = fmaf(w1, ed, a1[q]);
                }
            }
#pragma unroll
            for (int q = 0; q < 8; ++q) {
                float v0 = a0[q], v1 = a1[q];
                v0 = v0 * 0.5f * (1.0f + erff(v0 * 0.70710678118654752f));
                v1 = v1 * 0.5f * (1.0f + erff(v1 * 0.70710678118654752f));
                int erow = eb + q;
                *(__half*)(smem + S_B1 + sw128((uint32_t)(erow * 128 + lane * 2)))        = __float2half_rn(v0);
                *(__half*)(smem + S_B1 + sw128((uint32_t)(erow * 128 + (lane + 32) * 2))) = __float2half_rn(v1);
            }
        }
        // tmp: lanes 0-15, 16 edges of this warp
        if (lane < 16) {
            int m = lane >> 1, l = lane & 1;
#pragma unroll 4
            for (int it = 0; it < 16; ++it) {
                int erow = pbase + it;
                int e = e0 + erow;
                int nbr = nidx[e];
                const float* frow = f + (size_t)nbr * 32 + m * 4;
                const float* brow = b1 + (size_t)e * 8;
                float t = 0.f;
#pragma unroll
                for (int d = 0; d < 4; ++d)
                    t = fmaf(frow[d], brow[d * 2 + l], t);
                tmp_s[erow * 16 + lane] = t;
            }
        }
    }
    __syncthreads();   // A tile + tmp complete (W1s reads done -> out_s free)

    // ---- GEMM warp tiling: wn = n-half (0/1), wm = m-quarter (0..3) ----
    const int wn = wid >> 2, wm = wid & 3;

    // A fragments: rows wm*32..wm*32+31 (2 m-tiles), 4 k-steps
    uint32_t aF[32];
    {
#pragma unroll
        for (int t = 0; t < 2; ++t) {
            uint32_t rowb = (uint32_t)(wm * 32 + t * 16 + (lane & 15)) * 128 + ((lane >> 4) << 4);
#pragma unroll
            for (int s = 0; s < 4; ++s)
                ldsm_x4(&aF[t * 16 + 4 * s], sb + S_B1 + sw128(rowb + 32 * s));
        }
    }

    const int er0 = wm * 32 + (lane >> 2);
    const int jq  = (lane & 3) * 2;

    // hoist tmp values (invariant across chunks): [rr][nt&1][2]
    float tv[16];
#pragma unroll
    for (int rr = 0; rr < 4; ++rr) {
        float2 ta = *(float2*)&tmp_s[(er0 + rr * 8) * 16 + jq];
        float2 tb = *(float2*)&tmp_s[(er0 + rr * 8) * 16 + 8 + jq];
        tv[rr * 4 + 0] = ta.x; tv[rr * 4 + 1] = ta.y;
        tv[rr * 4 + 2] = tb.x; tv[rr * 4 + 3] = tb.y;
    }

    CPA_WAIT0();       // B0 + bl arrived
    __syncthreads();   // all warps done reading A -> S_B1 reusable as B buf

    float acc0 = 0.f, acc1 = 0.f, acc2 = 0.f, acc3 = 0.f;

#pragma unroll 1
    for (int ch = 0; ch < 6; ++ch) {
        const uint32_t bufC = (ch & 1) ? (sb + S_B1) : (sb + S_B0);
        if (ch < 5) {
            uint32_t bufN = (ch & 1) ? (sb + S_B0) : (sb + S_B1);
            const unsigned char* src = g_w2p + (size_t)(ch + 1) * 32768;
            for (int i = tid; i < 2048; i += 256) cpa16(bufN + i * 16, src + i * 16);
            CPA_COMMIT();
        }

#pragma unroll 2
        for (int nt = 0; nt < 8; ++nt) {
            const int nb = wn * 64 + nt * 8;    // col base within chunk
            uint32_t bH[8], bL[8];
            uint32_t rb = (uint32_t)(nb + (lane & 7)) * 128 + ((lane >> 3) << 4);
#pragma unroll
            for (int p = 0; p < 2; ++p) {
                uint32_t off = sw128(rb + 64 * p);
                ldsm_x4(&bH[4 * p], bufC + off);
                ldsm_x4(&bL[4 * p], bufC + 16384 + off);
            }

            // 4 independent chains: (m-tile 0/1) x (hi/lo)
            float cH0[4] = {0,0,0,0}, cL0[4] = {0,0,0,0};
            float cH1[4] = {0,0,0,0}, cL1[4] = {0,0,0,0};
#pragma unroll
            for (int s = 0; s < 4; ++s) {
                mma16816h(cH0, &aF[4 * s],      &bH[2 * s]);
                mma16816h(cL0, &aF[4 * s],      &bL[2 * s]);
                mma16816h(cH1, &aF[16 + 4 * s], &bH[2 * s]);
                mma16816h(cL1, &aF[16 + 4 * s], &bL[2 * s]);
            }

            const int g0 = ch * 128 + nb + jq;
            const int sel = (nt & 1) << 1;     // 0 (even nt) / 2 (odd nt)
            float2 blv = *(float2*)&bl_s[g0];
            acc0 += (cH0[0] + cL0[0] + blv.x) * tv[sel]      + (cH0[1] + cL0[1] + blv.y) * tv[sel + 1];
            acc1 += (cH0[2] + cL0[2] + blv.x) * tv[4 + sel]  + (cH0[3] + cL0[3] + blv.y) * tv[4 + sel + 1];
            acc2 += (cH1[0] + cL1[0] + blv.x) * tv[8 + sel]  + (cH1[1] + cL1[1] + blv.y) * tv[8 + sel + 1];
            acc3 += (cH1[2] + cL1[2] + blv.x) * tv[12 + sel] + (cH1[3] + cL1[3] + blv.y) * tv[12 + sel + 1];

            if (nt & 1) {
                acc0 += __shfl_xor_sync(0xffffffffu, acc0, 1);
                acc0 += __shfl_xor_sync(0xffffffffu, acc0, 2);
                acc1 += __shfl_xor_sync(0xffffffffu, acc1, 1);
                acc1 += __shfl_xor_sync(0xffffffffu, acc1, 2);
                acc2 += __shfl_xor_sync(0xffffffffu, acc2, 1);
                acc2 += __shfl_xor_sync(0xffffffffu, acc2, 2);
                acc3 += __shfl_xor_sync(0xffffffffu, acc3, 1);
                acc3 += __shfl_xor_sync(0xffffffffu, acc3, 2);
                if ((lane & 3) == 0) {
                    int i = ch * 8 + wn * 4 + (nt >> 1);
                    out_s[er0 * 49 + i]        = acc0;
                    out_s[(er0 + 8) * 49 + i]  = acc1;
                    out_s[(er0 + 16) * 49 + i] = acc2;
                    out_s[(er0 + 24) * 49 + i] = acc3;
                }
                acc0 = 0.f; acc1 = 0.f; acc2 = 0.f; acc3 = 0.f;
            }
        }

        if (ch < 5) {
            CPA_WAIT0();
            __syncthreads();
        }
    }
    __syncthreads();   // out_s complete; B buffers dead -> sc_s/v_s overlay

    // ---- per-edge: qkv = out48.reshape(24,2) @ b2f -> scores + v (to smem) ----
    float* sc_s = (float*)(smem + SV_SC);
    float* v_s  = (float*)(smem + SV_V);
    if (tid < 128) {
        int e = e0 + tid;
        const float* o48 = out_s + tid * 49;
        float bb[8];
#pragma unroll
        for (int x = 0; x < 8; ++x) bb[x] = b2[(size_t)e * 8 + x];

#pragma unroll
        for (int h = 0; h < 4; ++h) {
            float s = 0.f;
#pragma unroll
            for (int mm = 0; mm < 2; ++mm) {
                int m = 2 * h + mm;
#pragma unroll
                for (int d = 0; d < 4; ++d) {
                    float q = o48[m * 2]       * bb[d] + o48[m * 2 + 1]       * bb[4 + d];
                    float k = o48[(8 + m) * 2] * bb[d] + o48[(8 + m) * 2 + 1] * bb[4 + d];
                    s = fmaf(q, k, s);
                }
            }
            sc_s[tid * 4 + h] = s * 0.35355339059327376f;
        }
#pragma unroll
        for (int m = 0; m < 8; ++m)
#pragma unroll
            for (int d = 0; d < 4; ++d)
                v_s[tid * 32 + m * 4 + d] =
                    o48[(16 + m) * 2] * bb[d] + o48[(16 + m) * 2 + 1] * bb[4 + d];
    }
    __syncthreads();

    // ---- per-node attention: warp wid handles node blockIdx.x*8 + wid ----
    {
        float* outsm = (float*)(smem + S_TMP) + wid * 33;   // overlay on tmp_s
        int n = blockIdx.x * 8 + wid;
        int nb = wid * 16;   // node's first local edge

        float2 sc2 = *(float2*)&sc_s[nb * 4 + lane * 2];
        float s0 = sc2.x, s1 = sc2.y;

        float m0 = s0, m1 = s1;
#pragma unroll
        for (int off = 2; off < 32; off <<= 1) {
            m0 = fmaxf(m0, __shfl_xor_sync(0xffffffffu, m0, off));
            m1 = fmaxf(m1, __shfl_xor_sync(0xffffffffu, m1, off));
        }
        float e0v = expf(s0 - m0), e1v = expf(s1 - m1);
        float z0 = e0v, z1 = e1v;
#pragma unroll
        for (int off = 2; off < 32; off <<= 1) {
            z0 += __shfl_xor_sync(0xffffffffu, z0, off);
            z1 += __shfl_xor_sync(0xffffffffu, z1, off);
        }
        float a0 = e0v / z0, a1 = e1v / z1;

        const int m_mine = lane & 7;
        const int hsel   = (m_mine >> 1) & 1;
        float r[4] = {0.f, 0.f, 0.f, 0.f};
#pragma unroll
        for (int it = 0; it < 4; ++it) {
            float4 vv = *(float4*)&v_s[nb * 32 + it * 128 + lane * 4];
            int lsrc = 8 * it + ((lane >> 3) << 1) + ((lane >> 2) & 1);
            float av0 = __shfl_sync(0xffffffffu, a0, lsrc);
            float av1 = __shfl_sync(0xffffffffu, a1, lsrc);
            float a = hsel ? av1 : av0;
            r[0] = fmaf(a, vv.x, r[0]);
            r[1] = fmaf(a, vv.y, r[1]);
            r[2] = fmaf(a, vv.z, r[2]);
            r[3] = fmaf(a, vv.w, r[3]);
        }
#pragma unroll
        for (int off = 8; off < 32; off <<= 1)
#pragma unroll
            for (int d = 0; d < 4; ++d)
                r[d] += __shfl_xor_sync(0xffffffffu, r[d], off);

        if (lane < 8) {
#pragma unroll
            for (int d = 0; d < 4; ++d)
                outsm[m_mine * 4 + d] = r[d];
        }
        __syncwarp();

        int mm = lane >> 2, dd = lane & 3;
        int o = (dd == 0) ? mm : 8 + mm;
        float val = (dd == 0) ? bias[mm] : 0.f;
#pragma unroll
        for (int mp = 0; mp < 8; ++mp)
            val = fmaf(Wout[o * 8 + mp], outsm[mp * 4 + dd], val);
        out[(size_t)n * 32 + lane] = val;
    }
}

// ---------------- launcher ----------------------------------------------------
extern "C" void kernel_launch(void* const* d_in, const int* in_sizes, int n_in,
                              void* d_out, int out_size) {
    const float* b1   = (const float*)d_in[0];
    const float* b2   = (const float*)d_in[1];
    const float* ef   = (const float*)d_in[2];
    const float* f    = (const float*)d_in[3];
    const int*   nidx = (const int*)  d_in[4];
    const float* W1   = (const float*)d_in[5];
    const float* b1l  = (const float*)d_in[6];
    const float* W2   = (const float*)d_in[7];
    const float* b2l  = (const float*)d_in[8];
    const float* Wout = (const float*)d_in[9];
    const float* bias = (const float*)d_in[10];
    float* out = (float*)d_out;
    (void)in_sizes; (void)n_in; (void)out_size;

    cudaFuncSetAttribute(k2_fused, cudaFuncAttributeMaxDynamicSharedMemorySize, S_TOT);

    k0_w2prep<<<(768 * 64 + 255) / 256, 256>>>(W2);
    k2_fused<<<NTILES, 256, S_TOT>>>(ef, W1, b1l, f, nidx, b1, b2, b2l, Wout, bias, out);
}

// round 9
// speedup vs baseline: 3.4054x; 1.0029x over previous
#include <cuda_runtime.h>
#include <cuda_fp16.h>
#include <math.h>
#include <stdint.h>

#define NNODES 10000
#define KNBR   16
#define NEDGE  (NNODES * KNBR)
#define NTILES (NEDGE / 128)          // 1250

// ---------------- scratch (static device globals; no allocation) ------------
__device__ __align__(16) unsigned char g_w2p[12 * 16384];   // W2 [chunk][hi/lo] fp16 SW128 tiles
__device__ __align__(16) uint32_t g_w1f[2048];              // W1 B-fragments [nt][term][lane][4]

// ---------------- helpers ----------------------------------------------------
__device__ __forceinline__ uint32_t sw128(uint32_t o) { return o ^ ((o >> 3) & 0x70u); }

__device__ __forceinline__ uint32_t smem_u32(const void* p) {
    uint32_t a;
    asm("{ .reg .u64 t; cvta.to.shared.u64 t, %1; cvt.u32.u64 %0, t; }" : "=r"(a) : "l"(p));
    return a;
}
__device__ __forceinline__ void ldsm_x4(uint32_t* r, uint32_t addr) {
    asm volatile("ldmatrix.sync.aligned.m8n8.x4.shared.b16 {%0,%1,%2,%3}, [%4];"
                 : "=r"(r[0]), "=r"(r[1]), "=r"(r[2]), "=r"(r[3]) : "r"(addr));
}
__device__ __forceinline__ void mma16816h(float* c, const uint32_t* a, const uint32_t* b) {
    asm volatile(
        "mma.sync.aligned.m16n8k16.row.col.f32.f16.f16.f32 "
        "{%0,%1,%2,%3}, {%4,%5,%6,%7}, {%8,%9}, {%0,%1,%2,%3};"
        : "+f"(c[0]), "+f"(c[1]), "+f"(c[2]), "+f"(c[3])
        : "r"(a[0]), "r"(a[1]), "r"(a[2]), "r"(a[3]), "r"(b[0]), "r"(b[1]));
}
__device__ __forceinline__ void cpa16(uint32_t dst, const void* src) {
    asm volatile("cp.async.cg.shared.global [%0], [%1], 16;" :: "r"(dst), "l"(src));
}
#define CPA_COMMIT() asm volatile("cp.async.commit_group;" ::: "memory")
#define CPA_WAIT0()  asm volatile("cp.async.wait_group 0;" ::: "memory")

__device__ __forceinline__ uint32_t packh2(float x, float y) {
    __half2 h = __floats2half2_rn(x, y);
    return *(uint32_t*)&h;
}
__device__ __forceinline__ float gelu_exact(float v) {
    return v * 0.5f * (1.0f + erff(v * 0.70710678118654752f));
}

// ---------------- kernel 0: W2 split/swizzle + W1 fragment table -------------
__global__ void k0_prep(const float* __restrict__ W2, const float* __restrict__ W1) {
    int idx = blockIdx.x * 256 + threadIdx.x;
    if (idx < 2048) {   // W1 B-fragments: idx = ((nt*2+term)*32+lane)*4 + comp
        int comp = idx & 3, lane = (idx >> 2) & 31, term = (idx >> 7) & 1, nt = idx >> 8;
        int n = nt * 8 + (lane >> 2);
        int s = comp >> 1, reg = comp & 1;
        int kb = s * 16 + (lane & 3) * 2 + reg * 8;
        float v0 = W1[n * 32 + kb], v1 = W1[n * 32 + kb + 1];
        if (term == 0) {
            g_w1f[idx] = packh2(v0, v1);
        } else {
            float r0 = v0 - __half2float(__float2half_rn(v0));
            float r1 = v1 - __half2float(__float2half_rn(v1));
            g_w1f[idx] = packh2(r0, r1);
        }
    }
    if (idx >= 768 * 64) return;
    int r = idx >> 6, c = idx & 63;
    int ch = r >> 7, n = r & 127;
    float x = W2[idx];
    __half hi = __float2half_rn(x);
    __half lo = __float2half_rn(x - __half2float(hi));
    uint32_t off = sw128((uint32_t)(n * 128 + c * 2));
    *(__half*)(g_w2p + (size_t)(ch * 2 + 0) * 16384 + off) = hi;
    *(__half*)(g_w2p + (size_t)(ch * 2 + 1) * 16384 + off) = lo;
}

// ---------------- kernel 2: fully fused edge pipeline -------------------------
#define S_TMP  0                    // 8192  (tmp 128x16 f32; outsm overlay later)
#define S_BL   8192                 // 3072
#define S_B0   11264                // 32768 (B buf0; sc_s/v_s overlay in epilogue)
#define S_B1   44032                // 32768 (B buf1)
#define S_OUT  76800                // 25088 (out 128x49)
#define S_TOT  101888

#define SV_SC  (S_B0)               // sc_s: 128*4 f32 = 2048
#define SV_V   (S_B0 + 2048)        // v_s: 128*32 f32 = 16384

__global__ void __launch_bounds__(256, 2)
k2_fused(const float* __restrict__ ef,
         const float* __restrict__ b1lin,
         const float* __restrict__ f,
         const int*   __restrict__ nidx,
         const float* __restrict__ b1,
         const float* __restrict__ b2,
         const float* __restrict__ b2l,
         const float* __restrict__ Wout,
         const float* __restrict__ bias,
         float* __restrict__ out) {
    extern __shared__ __align__(1024) unsigned char smem[];
    const uint32_t sb = smem_u32(smem);
    float* tmp_s = (float*)(smem + S_TMP);
    float* bl_s  = (float*)(smem + S_BL);
    float* out_s = (float*)(smem + S_OUT);

    const int tid = threadIdx.x, wid = tid >> 5, lane = tid & 31;
    const int e0 = blockIdx.x << 7;
    const int wn = wid >> 2, wm = wid & 3;

    // ---- async staging: bl (3KB) + B chunk0 (32KB) -------------------------
    if (tid < 192) cpa16(sb + S_BL + tid * 16, (const unsigned char*)b2l + tid * 16);
    for (int i = tid; i < 2048; i += 256) cpa16(sb + S_B0 + i * 16, g_w2p + i * 16);
    CPA_COMMIT();

    // ---- MLP via HMMA: ef fragments (A) straight from gmem, hi/lo split ----
    // rows wm*32..+31; aef index: [t*8 + s*4 + c], c: {r0 klo, r1 klo, r0 khi, r1 khi}
    uint32_t aefH[16], aefL[16];
    {
        const int r0g = e0 + wm * 32 + (lane >> 2);
        const int kq = (lane & 3) * 2;
#pragma unroll
        for (int t = 0; t < 2; ++t)
#pragma unroll
            for (int s = 0; s < 2; ++s)
#pragma unroll
                for (int c = 0; c < 4; ++c) {
                    int rr = c & 1, ks = c >> 1;
                    int row = r0g + t * 16 + rr * 8;
                    int kk = s * 16 + ks * 8 + kq;
                    float2 v = *(const float2*)&ef[(size_t)row * 32 + kk];
                    float h0 = __half2float(__float2half_rn(v.x));
                    float h1 = __half2float(__float2half_rn(v.y));
                    aefH[t * 8 + s * 4 + c] = packh2(v.x, v.y);
                    aefL[t * 8 + s * 4 + c] = packh2(v.x - h0, v.y - h1);
                }
    }

    // ---- h-GEMM (3-term split) + bias + gelu -> main-GEMM A fragments ------
    uint32_t aF[32];
#pragma unroll
    for (int nt = 0; nt < 8; ++nt) {
        uint4 wH = *(const uint4*)&g_w1f[(nt * 2 + 0) * 128 + lane * 4];
        uint4 wL = *(const uint4*)&g_w1f[(nt * 2 + 1) * 128 + lane * 4];
        uint32_t bh0[2] = {wH.x, wH.y}, bh1[2] = {wH.z, wH.w};
        uint32_t bl0[2] = {wL.x, wL.y}, bl1[2] = {wL.z, wL.w};
        float2 bl2 = *(const float2*)&b1lin[nt * 8 + (lane & 3) * 2];
#pragma unroll
        for (int t = 0; t < 2; ++t) {
            float c[4] = {0.f, 0.f, 0.f, 0.f};
            mma16816h(c, &aefH[t * 8 + 0], bh0);
            mma16816h(c, &aefL[t * 8 + 0], bh0);
            mma16816h(c, &aefH[t * 8 + 0], bl0);
            mma16816h(c, &aefH[t * 8 + 4], bh1);
            mma16816h(c, &aefL[t * 8 + 4], bh1);
            mma16816h(c, &aefH[t * 8 + 4], bl1);
            float v0 = gelu_exact(c[0] + bl2.x);
            float v1 = gelu_exact(c[1] + bl2.y);
            float v2 = gelu_exact(c[2] + bl2.x);
            float v3 = gelu_exact(c[3] + bl2.y);
            int base = t * 16 + 4 * (nt >> 1) + (nt & 1) * 2;
            aF[base]     = packh2(v0, v1);
            aF[base + 1] = packh2(v2, v3);
        }
    }

    // ---- tmp: lanes 0-15, 16 edges of this warp (unchanged, bit-exact) -----
    {
        const int pbase = wid * 16;
        if (lane < 16) {
            int m = lane >> 1, l = lane & 1;
#pragma unroll 4
            for (int it = 0; it < 16; ++it) {
                int erow = pbase + it;
                int e = e0 + erow;
                int nbr = nidx[e];
                const float* frow = f + (size_t)nbr * 32 + m * 4;
                const float* brow = b1 + (size_t)e * 8;
                float t = 0.f;
#pragma unroll
                for (int d = 0; d < 4; ++d)
                    t = fmaf(frow[d], brow[d * 2 + l], t);
                tmp_s[erow * 16 + lane] = t;
            }
        }
    }
    CPA_WAIT0();       // B0 + bl arrived
    __syncthreads();   // tmp_s complete + cp.async visible to all

    const int er0 = wm * 32 + (lane >> 2);
    const int jq  = (lane & 3) * 2;

    // hoist tmp values (invariant across chunks)
    float tv[16];
#pragma unroll
    for (int rr = 0; rr < 4; ++rr) {
        float2 ta = *(float2*)&tmp_s[(er0 + rr * 8) * 16 + jq];
        float2 tb = *(float2*)&tmp_s[(er0 + rr * 8) * 16 + 8 + jq];
        tv[rr * 4 + 0] = ta.x; tv[rr * 4 + 1] = ta.y;
        tv[rr * 4 + 2] = tb.x; tv[rr * 4 + 3] = tb.y;
    }

    float acc0 = 0.f, acc1 = 0.f, acc2 = 0.f, acc3 = 0.f;

#pragma unroll 1
    for (int ch = 0; ch < 6; ++ch) {
        const uint32_t bufC = (ch & 1) ? (sb + S_B1) : (sb + S_B0);
        if (ch < 5) {
            uint32_t bufN = (ch & 1) ? (sb + S_B0) : (sb + S_B1);
            const unsigned char* src = g_w2p + (size_t)(ch + 1) * 32768;
            for (int i = tid; i < 2048; i += 256) cpa16(bufN + i * 16, src + i * 16);
            CPA_COMMIT();
        }

#pragma unroll 2
        for (int nt = 0; nt < 8; ++nt) {
            const int nb = wn * 64 + nt * 8;    // col base within chunk
            uint32_t bH[8], bL[8];
            uint32_t rb = (uint32_t)(nb + (lane & 7)) * 128 + ((lane >> 3) << 4);
#pragma unroll
            for (int p = 0; p < 2; ++p) {
                uint32_t off = sw128(rb + 64 * p);
                ldsm_x4(&bH[4 * p], bufC + off);
                ldsm_x4(&bL[4 * p], bufC + 16384 + off);
            }

            // 4 independent chains: (m-tile 0/1) x (hi/lo)
            float cH0[4] = {0,0,0,0}, cL0[4] = {0,0,0,0};
            float cH1[4] = {0,0,0,0}, cL1[4] = {0,0,0,0};
#pragma unroll
            for (int s = 0; s < 4; ++s) {
                mma16816h(cH0, &aF[4 * s],      &bH[2 * s]);
                mma16816h(cL0, &aF[4 * s],      &bL[2 * s]);
                mma16816h(cH1, &aF[16 + 4 * s], &bH[2 * s]);
                mma16816h(cL1, &aF[16 + 4 * s], &bL[2 * s]);
            }

            const int g0 = ch * 128 + nb + jq;
            const int sel = (nt & 1) << 1;
            float2 blv = *(float2*)&bl_s[g0];
            acc0 += (cH0[0] + cL0[0] + blv.x) * tv[sel]      + (cH0[1] + cL0[1] + blv.y) * tv[sel + 1];
            acc1 += (cH0[2] + cL0[2] + blv.x) * tv[4 + sel]  + (cH0[3] + cL0[3] + blv.y) * tv[4 + sel + 1];
            acc2 += (cH1[0] + cL1[0] + blv.x) * tv[8 + sel]  + (cH1[1] + cL1[1] + blv.y) * tv[8 + sel + 1];
            acc3 += (cH1[2] + cL1[2] + blv.x) * tv[12 + sel] + (cH1[3] + cL1[3] + blv.y) * tv[12 + sel + 1];

            if (nt & 1) {
                acc0 += __shfl_xor_sync(0xffffffffu, acc0, 1);
                acc0 += __shfl_xor_sync(0xffffffffu, acc0, 2);
                acc1 += __shfl_xor_sync(0xffffffffu, acc1, 1);
                acc1 += __shfl_xor_sync(0xffffffffu, acc1, 2);
                acc2 += __shfl_xor_sync(0xffffffffu, acc2, 1);
                acc2 += __shfl_xor_sync(0xffffffffu, acc2, 2);
                acc3 += __shfl_xor_sync(0xffffffffu, acc3, 1);
                acc3 += __shfl_xor_sync(0xffffffffu, acc3, 2);
                if ((lane & 3) == 0) {
                    int i = ch * 8 + wn * 4 + (nt >> 1);
                    out_s[er0 * 49 + i]        = acc0;
                    out_s[(er0 + 8) * 49 + i]  = acc1;
                    out_s[(er0 + 16) * 49 + i] = acc2;
                    out_s[(er0 + 24) * 49 + i] = acc3;
                }
                acc0 = 0.f; acc1 = 0.f; acc2 = 0.f; acc3 = 0.f;
            }
        }

        if (ch < 5) {
            CPA_WAIT0();
            __syncthreads();
        }
    }
    __syncthreads();   // out_s complete; B buffers dead -> sc_s/v_s overlay

    // ---- per-edge: qkv = out48.reshape(24,2) @ b2f -> scores + v (to smem) ----
    float* sc_s = (float*)(smem + SV_SC);
    float* v_s  = (float*)(smem + SV_V);
    if (tid < 128) {
        int e = e0 + tid;
        const float* o48 = out_s + tid * 49;
        float bb[8];
#pragma unroll
        for (int x = 0; x < 8; ++x) bb[x] = b2[(size_t)e * 8 + x];

#pragma unroll
        for (int h = 0; h < 4; ++h) {
            float s = 0.f;
#pragma unroll
            for (int mm = 0; mm < 2; ++mm) {
                int m = 2 * h + mm;
#pragma unroll
                for (int d = 0; d < 4; ++d) {
                    float q = o48[m * 2]       * bb[d] + o48[m * 2 + 1]       * bb[4 + d];
                    float k = o48[(8 + m) * 2] * bb[d] + o48[(8 + m) * 2 + 1] * bb[4 + d];
                    s = fmaf(q, k, s);
                }
            }
            sc_s[tid * 4 + h] = s * 0.35355339059327376f;
        }
#pragma unroll
        for (int m = 0; m < 8; ++m)
#pragma unroll
            for (int d = 0; d < 4; ++d)
                v_s[tid * 32 + m * 4 + d] =
                    o48[(16 + m) * 2] * bb[d] + o48[(16 + m) * 2 + 1] * bb[4 + d];
    }
    __syncthreads();

    // ---- per-node attention: warp wid handles node blockIdx.x*8 + wid ----
    {
        float* outsm = (float*)(smem + S_TMP) + wid * 33;   // overlay on tmp_s
        int n = blockIdx.x * 8 + wid;
        int nb = wid * 16;

        float2 sc2 = *(float2*)&sc_s[nb * 4 + lane * 2];
        float s0 = sc2.x, s1 = sc2.y;

        float m0 = s0, m1 = s1;
#pragma unroll
        for (int off = 2; off < 32; off <<= 1) {
            m0 = fmaxf(m0, __shfl_xor_sync(0xffffffffu, m0, off));
            m1 = fmaxf(m1, __shfl_xor_sync(0xffffffffu, m1, off));
        }
        float e0v = expf(s0 - m0), e1v = expf(s1 - m1);
        float z0 = e0v, z1 = e1v;
#pragma unroll
        for (int off = 2; off < 32; off <<= 1) {
            z0 += __shfl_xor_sync(0xffffffffu, z0, off);
            z1 += __shfl_xor_sync(0xffffffffu, z1, off);
        }
        float a0 = e0v / z0, a1 = e1v / z1;

        const int m_mine = lane & 7;
        const int hsel   = (m_mine >> 1) & 1;
        float r[4] = {0.f, 0.f, 0.f, 0.f};
#pragma unroll
        for (int it = 0; it < 4; ++it) {
            float4 vv = *(float4*)&v_s[nb * 32 + it * 128 + lane * 4];
            int lsrc = 8 * it + ((lane >> 3) << 1) + ((lane >> 2) & 1);
            float av0 = __shfl_sync(0xffffffffu, a0, lsrc);
            float av1 = __shfl_sync(0xffffffffu, a1, lsrc);
            float a = hsel ? av1 : av0;
            r[0] = fmaf(a, vv.x, r[0]);
            r[1] = fmaf(a, vv.y, r[1]);
            r[2] = fmaf(a, vv.z, r[2]);
            r[3] = fmaf(a, vv.w, r[3]);
        }
#pragma unroll
        for (int off = 8; off < 32; off <<= 1)
#pragma unroll
            for (int d = 0; d < 4; ++d)
                r[d] += __shfl_xor_sync(0xffffffffu, r[d], off);

        if (lane < 8) {
#pragma unroll
            for (int d = 0; d < 4; ++d)
                outsm[m_mine * 4 + d] = r[d];
        }
        __syncwarp();

        int mm = lane >> 2, dd = lane & 3;
        int o = (dd == 0) ? mm : 8 + mm;
        float val = (dd == 0) ? bias[mm] : 0.f;
#pragma unroll
        for (int mp = 0; mp < 8; ++mp)
            val = fmaf(Wout[o * 8 + mp], outsm[mp * 4 + dd], val);
        out[(size_t)n * 32 + lane] = val;
    }
}

// ---------------- launcher ----------------------------------------------------
extern "C" void kernel_launch(void* const* d_in, const int* in_sizes, int n_in,
                              void* d_out, int out_size) {
    const float* b1   = (const float*)d_in[0];
    const float* b2   = (const float*)d_in[1];
    const float* ef   = (const float*)d_in[2];
    const float* f    = (const float*)d_in[3];
    const int*   nidx = (const int*)  d_in[4];
    const float* W1   = (const float*)d_in[5];
    const float* b1l  = (const float*)d_in[6];
    const float* W2   = (const float*)d_in[7];
    const float* b2l  = (const float*)d_in[8];
    const float* Wout = (const float*)d_in[9];
    const float* bias = (const float*)d_in[10];
    float* out = (float*)d_out;
    (void)in_sizes; (void)n_in; (void)out_size;

    cudaFuncSetAttribute(k2_fused, cudaFuncAttributeMaxDynamicSharedMemorySize, S_TOT);

    k0_prep<<<(768 * 64 + 255) / 256, 256>>>(W2, W1);
    k2_fused<<<NTILES, 256, S_TOT>>>(ef, b1l, f, nidx, b1, b2, b2l, Wout, bias, out);
}

// round 10
// speedup vs baseline: 3.4170x; 1.0034x over previous
#include <cuda_runtime.h>
#include <cuda_fp16.h>
#include <math.h>
#include <stdint.h>

#define NNODES 10000
#define KNBR   16
#define NEDGE  (NNODES * KNBR)
#define NTILES (NEDGE / 128)          // 1250

// ---------------- scratch (static device globals; no allocation) ------------
__device__ __align__(16) unsigned char g_w2p[12 * 16384];   // W2 [chunk][hi/lo] fp16 SW128 tiles
__device__ __align__(16) uint32_t g_w1f[2048];              // W1 B-fragments [nt][term][lane][4]

// ---------------- helpers ----------------------------------------------------
__device__ __forceinline__ uint32_t sw128(uint32_t o) { return o ^ ((o >> 3) & 0x70u); }

__device__ __forceinline__ uint32_t smem_u32(const void* p) {
    uint32_t a;
    asm("{ .reg .u64 t; cvta.to.shared.u64 t, %1; cvt.u32.u64 %0, t; }" : "=r"(a) : "l"(p));
    return a;
}
__device__ __forceinline__ void ldsm_x4(uint32_t* r, uint32_t addr) {
    asm volatile("ldmatrix.sync.aligned.m8n8.x4.shared.b16 {%0,%1,%2,%3}, [%4];"
                 : "=r"(r[0]), "=r"(r[1]), "=r"(r[2]), "=r"(r[3]) : "r"(addr));
}
__device__ __forceinline__ void mma16816h(float* c, const uint32_t* a, const uint32_t* b) {
    asm volatile(
        "mma.sync.aligned.m16n8k16.row.col.f32.f16.f16.f32 "
        "{%0,%1,%2,%3}, {%4,%5,%6,%7}, {%8,%9}, {%0,%1,%2,%3};"
        : "+f"(c[0]), "+f"(c[1]), "+f"(c[2]), "+f"(c[3])
        : "r"(a[0]), "r"(a[1]), "r"(a[2]), "r"(a[3]), "r"(b[0]), "r"(b[1]));
}
__device__ __forceinline__ void cpa16(uint32_t dst, const void* src) {
    asm volatile("cp.async.cg.shared.global [%0], [%1], 16;" :: "r"(dst), "l"(src));
}
#define CPA_COMMIT() asm volatile("cp.async.commit_group;" ::: "memory")
#define CPA_WAIT0()  asm volatile("cp.async.wait_group 0;" ::: "memory")

__device__ __forceinline__ uint32_t packh2(float x, float y) {
    __half2 h = __floats2half2_rn(x, y);
    return *(uint32_t*)&h;
}
__device__ __forceinline__ float gelu_exact(float v) {
    return v * 0.5f * (1.0f + erff(v * 0.70710678118654752f));
}

// ---------------- kernel 0: W2 split/swizzle + W1 fragment table -------------
__global__ void k0_prep(const float* __restrict__ W2, const float* __restrict__ W1) {
    int idx = blockIdx.x * 256 + threadIdx.x;
    if (idx < 2048) {   // W1 B-fragments: idx = ((nt*2+term)*32+lane)*4 + comp
        int comp = idx & 3, lane = (idx >> 2) & 31, term = (idx >> 7) & 1, nt = idx >> 8;
        int n = nt * 8 + (lane >> 2);
        int s = comp >> 1, reg = comp & 1;
        int kb = s * 16 + (lane & 3) * 2 + reg * 8;
        float v0 = W1[n * 32 + kb], v1 = W1[n * 32 + kb + 1];
        if (term == 0) {
            g_w1f[idx] = packh2(v0, v1);
        } else {
            float r0 = v0 - __half2float(__float2half_rn(v0));
            float r1 = v1 - __half2float(__float2half_rn(v1));
            g_w1f[idx] = packh2(r0, r1);
        }
    }
    if (idx >= 768 * 64) return;
    int r = idx >> 6, c = idx & 63;
    int ch = r >> 7, n = r & 127;
    float x = W2[idx];
    __half hi = __float2half_rn(x);
    __half lo = __float2half_rn(x - __half2float(hi));
    uint32_t off = sw128((uint32_t)(n * 128 + c * 2));
    *(__half*)(g_w2p + (size_t)(ch * 2 + 0) * 16384 + off) = hi;
    *(__half*)(g_w2p + (size_t)(ch * 2 + 1) * 16384 + off) = lo;
}

// ---------------- kernel 2: fully fused edge pipeline -------------------------
#define S_TMP  0                    // 8192  (tmp 128x16 f32; outsm overlay later)
#define S_BL   8192                 // 3072
#define S_B0   11264                // 32768 (B buf0; sc_s/v_s overlay in epilogue)
#define S_B1   44032                // 32768 (B buf1)
#define S_OUT  76800                // 25088 (out 128x49)
#define S_TOT  101888

#define SV_SC  (S_B0)               // sc_s: 128*4 f32 = 2048
#define SV_V   (S_B0 + 2048)        // v_s: 128*32 f32 = 16384

__global__ void __launch_bounds__(256, 2)
k2_fused(const float* __restrict__ ef,
         const float* __restrict__ b1lin,
         const float* __restrict__ f,
         const int*   __restrict__ nidx,
         const float* __restrict__ b1,
         const float* __restrict__ b2,
         const float* __restrict__ b2l,
         const float* __restrict__ Wout,
         const float* __restrict__ bias,
         float* __restrict__ out) {
    extern __shared__ __align__(1024) unsigned char smem[];
    const uint32_t sb = smem_u32(smem);
    float* tmp_s = (float*)(smem + S_TMP);
    float* bl_s  = (float*)(smem + S_BL);
    float* out_s = (float*)(smem + S_OUT);

    const int tid = threadIdx.x, wid = tid >> 5, lane = tid & 31;
    const int e0 = blockIdx.x << 7;
    const int wn = wid >> 2, wm = wid & 3;

    // ---- async staging: bl (3KB) + B chunk0 (32KB) -------------------------
    if (tid < 192) cpa16(sb + S_BL + tid * 16, (const unsigned char*)b2l + tid * 16);
    for (int i = tid; i < 2048; i += 256) cpa16(sb + S_B0 + i * 16, g_w2p + i * 16);
    CPA_COMMIT();

    // ---- MLP via HMMA: ef fragments (A) straight from gmem, hi/lo split ----
    uint32_t aF[32];
    {
        uint32_t aefH[16], aefL[16];
        const int r0g = e0 + wm * 32 + (lane >> 2);
        const int kq = (lane & 3) * 2;
#pragma unroll
        for (int t = 0; t < 2; ++t)
#pragma unroll
            for (int s = 0; s < 2; ++s)
#pragma unroll
                for (int c = 0; c < 4; ++c) {
                    int rr = c & 1, ks = c >> 1;
                    int row = r0g + t * 16 + rr * 8;
                    int kk = s * 16 + ks * 8 + kq;
                    float2 v = *(const float2*)&ef[(size_t)row * 32 + kk];
                    float h0 = __half2float(__float2half_rn(v.x));
                    float h1 = __half2float(__float2half_rn(v.y));
                    aefH[t * 8 + s * 4 + c] = packh2(v.x, v.y);
                    aefL[t * 8 + s * 4 + c] = packh2(v.x - h0, v.y - h1);
                }

        // ---- h-GEMM (3-term split) + bias + gelu -> main-GEMM A fragments --
#pragma unroll
        for (int nt = 0; nt < 8; ++nt) {
            uint4 wH = *(const uint4*)&g_w1f[(nt * 2 + 0) * 128 + lane * 4];
            uint4 wL = *(const uint4*)&g_w1f[(nt * 2 + 1) * 128 + lane * 4];
            uint32_t bh0[2] = {wH.x, wH.y}, bh1[2] = {wH.z, wH.w};
            uint32_t bl0[2] = {wL.x, wL.y}, bl1[2] = {wL.z, wL.w};
            float2 bl2 = *(const float2*)&b1lin[nt * 8 + (lane & 3) * 2];
#pragma unroll
            for (int t = 0; t < 2; ++t) {
                float c[4] = {0.f, 0.f, 0.f, 0.f};
                mma16816h(c, &aefH[t * 8 + 0], bh0);
                mma16816h(c, &aefL[t * 8 + 0], bh0);
                mma16816h(c, &aefH[t * 8 + 0], bl0);
                mma16816h(c, &aefH[t * 8 + 4], bh1);
                mma16816h(c, &aefL[t * 8 + 4], bh1);
                mma16816h(c, &aefH[t * 8 + 4], bl1);
                float v0 = gelu_exact(c[0] + bl2.x);
                float v1 = gelu_exact(c[1] + bl2.y);
                float v2 = gelu_exact(c[2] + bl2.x);
                float v3 = gelu_exact(c[3] + bl2.y);
                int base = t * 16 + 4 * (nt >> 1) + (nt & 1) * 2;
                aF[base]     = packh2(v0, v1);
                aF[base + 1] = packh2(v2, v3);
            }
        }
    }

    // ---- tmp: lanes 0-15, 16 edges of this warp (unchanged, bit-exact) -----
    {
        const int pbase = wid * 16;
        if (lane < 16) {
            int m = lane >> 1, l = lane & 1;
#pragma unroll 4
            for (int it = 0; it < 16; ++it) {
                int erow = pbase + it;
                int e = e0 + erow;
                int nbr = nidx[e];
                const float* frow = f + (size_t)nbr * 32 + m * 4;
                const float* brow = b1 + (size_t)e * 8;
                float t = 0.f;
#pragma unroll
                for (int d = 0; d < 4; ++d)
                    t = fmaf(frow[d], brow[d * 2 + l], t);
                tmp_s[erow * 16 + lane] = t;
            }
        }
    }
    CPA_WAIT0();       // B0 + bl arrived
    __syncthreads();   // tmp_s complete + cp.async visible to all

    const int er0 = wm * 32 + (lane >> 2);
    const int jq  = (lane & 3) * 2;

    // hoist tmp values (invariant across chunks)
    float tv[16];
#pragma unroll
    for (int rr = 0; rr < 4; ++rr) {
        float2 ta = *(float2*)&tmp_s[(er0 + rr * 8) * 16 + jq];
        float2 tb = *(float2*)&tmp_s[(er0 + rr * 8) * 16 + 8 + jq];
        tv[rr * 4 + 0] = ta.x; tv[rr * 4 + 1] = ta.y;
        tv[rr * 4 + 2] = tb.x; tv[rr * 4 + 3] = tb.y;
    }

    float acc0 = 0.f, acc1 = 0.f, acc2 = 0.f, acc3 = 0.f;

#pragma unroll 1
    for (int ch = 0; ch < 6; ++ch) {
        const uint32_t bufC = (ch & 1) ? (sb + S_B1) : (sb + S_B0);
        const uint32_t bufN = (ch & 1) ? (sb + S_B0) : (sb + S_B1);
        const unsigned char* srcN = g_w2p + (size_t)(ch + 1) * 32768;
        const bool pf = (ch < 5);

#pragma unroll 4
        for (int nt = 0; nt < 8; ++nt) {
            // spread next-chunk prefetch over nt=0..3 (2 cp.async per thread per nt)
            if (pf && nt < 4) {
                int i0 = tid + 256 * (2 * nt);
                int i1 = tid + 256 * (2 * nt + 1);
                cpa16(bufN + i0 * 16, srcN + i0 * 16);
                cpa16(bufN + i1 * 16, srcN + i1 * 16);
                if (nt == 3) CPA_COMMIT();
            }

            const int nb = wn * 64 + nt * 8;    // col base within chunk
            uint32_t bH[8], bL[8];
            uint32_t rb = (uint32_t)(nb + (lane & 7)) * 128 + ((lane >> 3) << 4);
#pragma unroll
            for (int p = 0; p < 2; ++p) {
                uint32_t off = sw128(rb + 64 * p);
                ldsm_x4(&bH[4 * p], bufC + off);
                ldsm_x4(&bL[4 * p], bufC + 16384 + off);
            }

            // 4 independent chains: (m-tile 0/1) x (hi/lo)
            float cH0[4] = {0,0,0,0}, cL0[4] = {0,0,0,0};
            float cH1[4] = {0,0,0,0}, cL1[4] = {0,0,0,0};
#pragma unroll
            for (int s = 0; s < 4; ++s) {
                mma16816h(cH0, &aF[4 * s],      &bH[2 * s]);
                mma16816h(cL0, &aF[4 * s],      &bL[2 * s]);
                mma16816h(cH1, &aF[16 + 4 * s], &bH[2 * s]);
                mma16816h(cL1, &aF[16 + 4 * s], &bL[2 * s]);
            }

            const int g0 = ch * 128 + nb + jq;
            const int sel = (nt & 1) << 1;
            float2 blv = *(float2*)&bl_s[g0];
            acc0 += (cH0[0] + cL0[0] + blv.x) * tv[sel]      + (cH0[1] + cL0[1] + blv.y) * tv[sel + 1];
            acc1 += (cH0[2] + cL0[2] + blv.x) * tv[4 + sel]  + (cH0[3] + cL0[3] + blv.y) * tv[4 + sel + 1];
            acc2 += (cH1[0] + cL1[0] + blv.x) * tv[8 + sel]  + (cH1[1] + cL1[1] + blv.y) * tv[8 + sel + 1];
            acc3 += (cH1[2] + cL1[2] + blv.x) * tv[12 + sel] + (cH1[3] + cL1[3] + blv.y) * tv[12 + sel + 1];

            if (nt & 1) {
                acc0 += __shfl_xor_sync(0xffffffffu, acc0, 1);
                acc0 += __shfl_xor_sync(0xffffffffu, acc0, 2);
                acc1 += __shfl_xor_sync(0xffffffffu, acc1, 1);
                acc1 += __shfl_xor_sync(0xffffffffu, acc1, 2);
                acc2 += __shfl_xor_sync(0xffffffffu, acc2, 1);
                acc2 += __shfl_xor_sync(0xffffffffu, acc2, 2);
                acc3 += __shfl_xor_sync(0xffffffffu, acc3, 1);
                acc3 += __shfl_xor_sync(0xffffffffu, acc3, 2);
                if ((lane & 3) == 0) {
                    int i = ch * 8 + wn * 4 + (nt >> 1);
                    out_s[er0 * 49 + i]        = acc0;
                    out_s[(er0 + 8) * 49 + i]  = acc1;
                    out_s[(er0 + 16) * 49 + i] = acc2;
                    out_s[(er0 + 24) * 49 + i] = acc3;
                }
                acc0 = 0.f; acc1 = 0.f; acc2 = 0.f; acc3 = 0.f;
            }
        }

        if (pf) {
            CPA_WAIT0();
            __syncthreads();
        }
    }
    __syncthreads();   // out_s complete; B buffers dead -> sc_s/v_s overlay

    // ---- per-edge: qkv = out48.reshape(24,2) @ b2f -> scores + v (to smem) ----
    float* sc_s = (float*)(smem + SV_SC);
    float* v_s  = (float*)(smem + SV_V);
    if (tid < 128) {
        int e = e0 + tid;
        const float* o48 = out_s + tid * 49;
        float bb[8];
#pragma unroll
        for (int x = 0; x < 8; ++x) bb[x] = b2[(size_t)e * 8 + x];

#pragma unroll
        for (int h = 0; h < 4; ++h) {
            float s = 0.f;
#pragma unroll
            for (int mm = 0; mm < 2; ++mm) {
                int m = 2 * h + mm;
#pragma unroll
                for (int d = 0; d < 4; ++d) {
                    float q = o48[m * 2]       * bb[d] + o48[m * 2 + 1]       * bb[4 + d];
                    float k = o48[(8 + m) * 2] * bb[d] + o48[(8 + m) * 2 + 1] * bb[4 + d];
                    s = fmaf(q, k, s);
                }
            }
            sc_s[tid * 4 + h] = s * 0.35355339059327376f;
        }
#pragma unroll
        for (int m = 0; m < 8; ++m)
#pragma unroll
            for (int d = 0; d < 4; ++d)
                v_s[tid * 32 + m * 4 + d] =
                    o48[(16 + m) * 2] * bb[d] + o48[(16 + m) * 2 + 1] * bb[4 + d];
    }
    __syncthreads();

    // ---- per-node attention: warp wid handles node blockIdx.x*8 + wid ----
    {
        float* outsm = (float*)(smem + S_TMP) + wid * 33;   // overlay on tmp_s
        int n = blockIdx.x * 8 + wid;
        int nb = wid * 16;

        float2 sc2 = *(float2*)&sc_s[nb * 4 + lane * 2];
        float s0 = sc2.x, s1 = sc2.y;

        float m0 = s0, m1 = s1;
#pragma unroll
        for (int off = 2; off < 32; off <<= 1) {
            m0 = fmaxf(m0, __shfl_xor_sync(0xffffffffu, m0, off));
            m1 = fmaxf(m1, __shfl_xor_sync(0xffffffffu, m1, off));
        }
        float e0v = expf(s0 - m0), e1v = expf(s1 - m1);
        float z0 = e0v, z1 = e1v;
#pragma unroll
        for (int off = 2; off < 32; off <<= 1) {
            z0 += __shfl_xor_sync(0xffffffffu, z0, off);
            z1 += __shfl_xor_sync(0xffffffffu, z1, off);
        }
        float a0 = e0v / z0, a1 = e1v / z1;

        const int m_mine = lane & 7;
        const int hsel   = (m_mine >> 1) & 1;
        float r[4] = {0.f, 0.f, 0.f, 0.f};
#pragma unroll
        for (int it = 0; it < 4; ++it) {
            float4 vv = *(float4*)&v_s[nb * 32 + it * 128 + lane * 4];
            int lsrc = 8 * it + ((lane >> 3) << 1) + ((lane >> 2) & 1);
            float av0 = __shfl_sync(0xffffffffu, a0, lsrc);
            float av1 = __shfl_sync(0xffffffffu, a1, lsrc);
            float a = hsel ? av1 : av0;
            r[0] = fmaf(a, vv.x, r[0]);
            r[1] = fmaf(a, vv.y, r[1]);
            r[2] = fmaf(a, vv.z, r[2]);
            r[3] = fmaf(a, vv.w, r[3]);
        }
#pragma unroll
        for (int off = 8; off < 32; off <<= 1)
#pragma unroll
            for (int d = 0; d < 4; ++d)
                r[d] += __shfl_xor_sync(0xffffffffu, r[d], off);

        if (lane < 8) {
#pragma unroll
            for (int d = 0; d < 4; ++d)
                outsm[m_mine * 4 + d] = r[d];
        }
        __syncwarp();

        int mm = lane >> 2, dd = lane & 3;
        int o = (dd == 0) ? mm : 8 + mm;
        float val = (dd == 0) ? bias[mm] : 0.f;
#pragma unroll
        for (int mp = 0; mp < 8; ++mp)
            val = fmaf(Wout[o * 8 + mp], outsm[mp * 4 + dd], val);
        out[(size_t)n * 32 + lane] = val;
    }
}

// ---------------- launcher ----------------------------------------------------
extern "C" void kernel_launch(void* const* d_in, const int* in_sizes, int n_in,
                              void* d_out, int out_size) {
    const float* b1   = (const float*)d_in[0];
    const float* b2   = (const float*)d_in[1];
    const float* ef   = (const float*)d_in[2];
    const float* f    = (const float*)d_in[3];
    const int*   nidx = (const int*)  d_in[4];
    const float* W1   = (const float*)d_in[5];
    const float* b1l  = (const float*)d_in[6];
    const float* W2   = (const float*)d_in[7];
    const float* b2l  = (const float*)d_in[8];
    const float* Wout = (const float*)d_in[9];
    const float* bias = (const float*)d_in[10];
    float* out = (float*)d_out;
    (void)in_sizes; (void)n_in; (void)out_size;

    cudaFuncSetAttribute(k2_fused, cudaFuncAttributeMaxDynamicSharedMemorySize, S_TOT);

    k0_prep<<<(768 * 64 + 255) / 256, 256>>>(W2, W1);
    k2_fused<<<NTILES, 256, S_TOT>>>(ef, b1l, f, nidx, b1, b2, b2l, Wout, bias, out);
}

// round 11
// speedup vs baseline: 3.6027x; 1.0544x over previous
#include <cuda_runtime.h>
#include <cuda_fp16.h>
#include <math.h>
#include <stdint.h>

#define NNODES 10000
#define KNBR   16
#define NEDGE  (NNODES * KNBR)
#define NTILES (NEDGE / 128)          // 1250

// ---------------- scratch (static device globals; no allocation) ------------
__device__ __align__(16) unsigned char g_w2p[12 * 16384];   // W2 [chunk][hi/lo] fp16 SW128 tiles
__device__ __align__(16) uint32_t g_w1f[2048];              // W1 B-fragments [nt][term][lane][4]

// ---------------- helpers ----------------------------------------------------
__device__ __forceinline__ uint32_t sw128(uint32_t o) { return o ^ ((o >> 3) & 0x70u); }

__device__ __forceinline__ uint32_t smem_u32(const void* p) {
    uint32_t a;
    asm("{ .reg .u64 t; cvta.to.shared.u64 t, %1; cvt.u32.u64 %0, t; }" : "=r"(a) : "l"(p));
    return a;
}
__device__ __forceinline__ void ldsm_x4(uint32_t* r, uint32_t addr) {
    asm volatile("ldmatrix.sync.aligned.m8n8.x4.shared.b16 {%0,%1,%2,%3}, [%4];"
                 : "=r"(r[0]), "=r"(r[1]), "=r"(r[2]), "=r"(r[3]) : "r"(addr));
}
__device__ __forceinline__ void mma16816h(float* c, const uint32_t* a, const uint32_t* b) {
    asm volatile(
        "mma.sync.aligned.m16n8k16.row.col.f32.f16.f16.f32 "
        "{%0,%1,%2,%3}, {%4,%5,%6,%7}, {%8,%9}, {%0,%1,%2,%3};"
        : "+f"(c[0]), "+f"(c[1]), "+f"(c[2]), "+f"(c[3])
        : "r"(a[0]), "r"(a[1]), "r"(a[2]), "r"(a[3]), "r"(b[0]), "r"(b[1]));
}
__device__ __forceinline__ void cpa16(uint32_t dst, const void* src) {
    asm volatile("cp.async.cg.shared.global [%0], [%1], 16;" :: "r"(dst), "l"(src));
}
#define CPA_COMMIT() asm volatile("cp.async.commit_group;" ::: "memory")
#define CPA_WAIT0()  asm volatile("cp.async.wait_group 0;" ::: "memory")

__device__ __forceinline__ uint32_t packh2(float x, float y) {
    __half2 h = __floats2half2_rn(x, y);
    return *(uint32_t*)&h;
}
// exact gelu (used in k0-independent contexts if needed)
__device__ __forceinline__ float gelu_exact(float v) {
    return v * 0.5f * (1.0f + erff(v * 0.70710678118654752f));
}
// fast gelu: A&S 7.1.25 erf, |abs err| <= 2.5e-5 (far below h's fp16 quantization)
__device__ __forceinline__ float gelu_fast(float v) {
    float x = fabsf(v) * 0.70710678118654752f;
    float w = fmaf(0.47047f, x, 1.0f);
    float t;
    asm("rcp.approx.f32 %0, %1;" : "=f"(t) : "f"(w));
    float P = t * fmaf(t, fmaf(t, 0.7478556f, -0.0958798f), 0.3480242f);
    float E = __expf(-x * x);
    float er = fmaf(-P, E, 1.0f);
    er = copysignf(er, v);
    return v * 0.5f * (1.0f + er);
}

// ---------------- kernel 0: W2 split/swizzle + W1 fragment table -------------
__global__ void k0_prep(const float* __restrict__ W2, const float* __restrict__ W1) {
    int idx = blockIdx.x * 256 + threadIdx.x;
    if (idx < 2048) {   // W1 B-fragments: idx = ((nt*2+term)*32+lane)*4 + comp
        int comp = idx & 3, lane = (idx >> 2) & 31, term = (idx >> 7) & 1, nt = idx >> 8;
        int n = nt * 8 + (lane >> 2);
        int s = comp >> 1, reg = comp & 1;
        int kb = s * 16 + (lane & 3) * 2 + reg * 8;
        float v0 = W1[n * 32 + kb], v1 = W1[n * 32 + kb + 1];
        if (term == 0) {
            g_w1f[idx] = packh2(v0, v1);
        } else {
            float r0 = v0 - __half2float(__float2half_rn(v0));
            float r1 = v1 - __half2float(__float2half_rn(v1));
            g_w1f[idx] = packh2(r0, r1);
        }
    }
    if (idx >= 768 * 64) return;
    int r = idx >> 6, c = idx & 63;
    int ch = r >> 7, n = r & 127;
    float x = W2[idx];
    __half hi = __float2half_rn(x);
    __half lo = __float2half_rn(x - __half2float(hi));
    uint32_t off = sw128((uint32_t)(n * 128 + c * 2));
    *(__half*)(g_w2p + (size_t)(ch * 2 + 0) * 16384 + off) = hi;
    *(__half*)(g_w2p + (size_t)(ch * 2 + 1) * 16384 + off) = lo;
}

// ---------------- kernel 2: fully fused edge pipeline -------------------------
#define S_TMP  0                    // 8192  (tmp 128x16 f32; outsm overlay later)
#define S_BL   8192                 // 3072
#define S_B0   11264                // 32768 (B buf0; sc_s/v_s overlay in epilogue)
#define S_B1   44032                // 32768 (B buf1)
#define S_OUT  76800                // 25088 (out 128x49)
#define S_TOT  101888

#define SV_SC  (S_B0)               // sc_s: 128*4 f32 = 2048
#define SV_V   (S_B0 + 2048)        // v_s: 128*32 f32 = 16384

__global__ void __launch_bounds__(256, 2)
k2_fused(const float* __restrict__ ef,
         const float* __restrict__ b1lin,
         const float* __restrict__ f,
         const int*   __restrict__ nidx,
         const float* __restrict__ b1,
         const float* __restrict__ b2,
         const float* __restrict__ b2l,
         const float* __restrict__ Wout,
         const float* __restrict__ bias,
         float* __restrict__ out) {
    extern __shared__ __align__(1024) unsigned char smem[];
    const uint32_t sb = smem_u32(smem);
    float* tmp_s = (float*)(smem + S_TMP);
    float* bl_s  = (float*)(smem + S_BL);
    float* out_s = (float*)(smem + S_OUT);

    const int tid = threadIdx.x, wid = tid >> 5, lane = tid & 31;
    const int e0 = blockIdx.x << 7;
    const int wn = wid >> 2, wm = wid & 3;

    // ---- async staging: bl (3KB) + B chunk0 (32KB) -------------------------
    if (tid < 192) cpa16(sb + S_BL + tid * 16, (const unsigned char*)b2l + tid * 16);
    for (int i = tid; i < 2048; i += 256) cpa16(sb + S_B0 + i * 16, g_w2p + i * 16);
    CPA_COMMIT();

    // ---- MLP via HMMA: ef fragments (A) straight from gmem, hi/lo split ----
    uint32_t aF[32];
    {
        uint32_t aefH[16], aefL[16];
        const int r0g = e0 + wm * 32 + (lane >> 2);
        const int kq = (lane & 3) * 2;
#pragma unroll
        for (int t = 0; t < 2; ++t)
#pragma unroll
            for (int s = 0; s < 2; ++s)
#pragma unroll
                for (int c = 0; c < 4; ++c) {
                    int rr = c & 1, ks = c >> 1;
                    int row = r0g + t * 16 + rr * 8;
                    int kk = s * 16 + ks * 8 + kq;
                    float2 v = *(const float2*)&ef[(size_t)row * 32 + kk];
                    float h0 = __half2float(__float2half_rn(v.x));
                    float h1 = __half2float(__float2half_rn(v.y));
                    aefH[t * 8 + s * 4 + c] = packh2(v.x, v.y);
                    aefL[t * 8 + s * 4 + c] = packh2(v.x - h0, v.y - h1);
                }

        // ---- h-GEMM (3-term split, bias in acc init) + gelu -> A fragments --
#pragma unroll
        for (int nt = 0; nt < 8; ++nt) {
            uint4 wH = *(const uint4*)&g_w1f[(nt * 2 + 0) * 128 + lane * 4];
            uint4 wL = *(const uint4*)&g_w1f[(nt * 2 + 1) * 128 + lane * 4];
            uint32_t bh0[2] = {wH.x, wH.y}, bh1[2] = {wH.z, wH.w};
            uint32_t bl0[2] = {wL.x, wL.y}, bl1[2] = {wL.z, wL.w};
            float2 bl2 = *(const float2*)&b1lin[nt * 8 + (lane & 3) * 2];
#pragma unroll
            for (int t = 0; t < 2; ++t) {
                float c[4] = {bl2.x, bl2.y, bl2.x, bl2.y};   // bias folded into acc
                mma16816h(c, &aefH[t * 8 + 0], bh0);
                mma16816h(c, &aefL[t * 8 + 0], bh0);
                mma16816h(c, &aefH[t * 8 + 0], bl0);
                mma16816h(c, &aefH[t * 8 + 4], bh1);
                mma16816h(c, &aefL[t * 8 + 4], bh1);
                mma16816h(c, &aefH[t * 8 + 4], bl1);
                float v0 = gelu_fast(c[0]);
                float v1 = gelu_fast(c[1]);
                float v2 = gelu_fast(c[2]);
                float v3 = gelu_fast(c[3]);
                int base = t * 16 + 4 * (nt >> 1) + (nt & 1) * 2;
                aF[base]     = packh2(v0, v1);
                aF[base + 1] = packh2(v2, v3);
            }
        }
    }

    // ---- tmp: lanes 0-15, 16 edges of this warp (unchanged, bit-exact) -----
    {
        const int pbase = wid * 16;
        if (lane < 16) {
            int m = lane >> 1, l = lane & 1;
#pragma unroll 4
            for (int it = 0; it < 16; ++it) {
                int erow = pbase + it;
                int e = e0 + erow;
                int nbr = nidx[e];
                const float* frow = f + (size_t)nbr * 32 + m * 4;
                const float* brow = b1 + (size_t)e * 8;
                float t = 0.f;
#pragma unroll
                for (int d = 0; d < 4; ++d)
                    t = fmaf(frow[d], brow[d * 2 + l], t);
                tmp_s[erow * 16 + lane] = t;
            }
        }
    }
    CPA_WAIT0();       // B0 + bl arrived
    __syncthreads();   // tmp_s complete + cp.async visible to all

    const int er0 = wm * 32 + (lane >> 2);
    const int jq  = (lane & 3) * 2;

    // hoist tmp values (invariant across chunks)
    float tv[16];
#pragma unroll
    for (int rr = 0; rr < 4; ++rr) {
        float2 ta = *(float2*)&tmp_s[(er0 + rr * 8) * 16 + jq];
        float2 tb = *(float2*)&tmp_s[(er0 + rr * 8) * 16 + 8 + jq];
        tv[rr * 4 + 0] = ta.x; tv[rr * 4 + 1] = ta.y;
        tv[rr * 4 + 2] = tb.x; tv[rr * 4 + 3] = tb.y;
    }

    float acc0 = 0.f, acc1 = 0.f, acc2 = 0.f, acc3 = 0.f;

#pragma unroll 1
    for (int ch = 0; ch < 6; ++ch) {
        const uint32_t bufC = (ch & 1) ? (sb + S_B1) : (sb + S_B0);
        const uint32_t bufN = (ch & 1) ? (sb + S_B0) : (sb + S_B1);
        const unsigned char* srcN = g_w2p + (size_t)(ch + 1) * 32768;
        const bool pf = (ch < 5);

#pragma unroll 4
        for (int nt = 0; nt < 8; ++nt) {
            // spread next-chunk prefetch over nt=0..3 (2 cp.async per thread per nt)
            if (pf && nt < 4) {
                int i0 = tid + 256 * (2 * nt);
                int i1 = tid + 256 * (2 * nt + 1);
                cpa16(bufN + i0 * 16, srcN + i0 * 16);
                cpa16(bufN + i1 * 16, srcN + i1 * 16);
                if (nt == 3) CPA_COMMIT();
            }

            const int nb = wn * 64 + nt * 8;    // col base within chunk
            uint32_t bH[8], bL[8];
            uint32_t rb = (uint32_t)(nb + (lane & 7)) * 128 + ((lane >> 3) << 4);
#pragma unroll
            for (int p = 0; p < 2; ++p) {
                uint32_t off = sw128(rb + 64 * p);
                ldsm_x4(&bH[4 * p], bufC + off);
                ldsm_x4(&bL[4 * p], bufC + 16384 + off);
            }

            // 2 chains (m-tile 0/1); hi+lo accumulate into same acc; bl in init
            const int g0 = ch * 128 + nb + jq;
            float2 blv = *(float2*)&bl_s[g0];
            float c0[4] = {blv.x, blv.y, blv.x, blv.y};
            float c1[4] = {blv.x, blv.y, blv.x, blv.y};
#pragma unroll
            for (int s = 0; s < 4; ++s) {
                mma16816h(c0, &aF[4 * s],      &bH[2 * s]);
                mma16816h(c0, &aF[4 * s],      &bL[2 * s]);
                mma16816h(c1, &aF[16 + 4 * s], &bH[2 * s]);
                mma16816h(c1, &aF[16 + 4 * s], &bL[2 * s]);
            }

            const int sel = (nt & 1) << 1;
            acc0 += c0[0] * tv[sel]      + c0[1] * tv[sel + 1];
            acc1 += c0[2] * tv[4 + sel]  + c0[3] * tv[4 + sel + 1];
            acc2 += c1[0] * tv[8 + sel]  + c1[1] * tv[8 + sel + 1];
            acc3 += c1[2] * tv[12 + sel] + c1[3] * tv[12 + sel + 1];

            if (nt & 1) {
                acc0 += __shfl_xor_sync(0xffffffffu, acc0, 1);
                acc0 += __shfl_xor_sync(0xffffffffu, acc0, 2);
                acc1 += __shfl_xor_sync(0xffffffffu, acc1, 1);
                acc1 += __shfl_xor_sync(0xffffffffu, acc1, 2);
                acc2 += __shfl_xor_sync(0xffffffffu, acc2, 1);
                acc2 += __shfl_xor_sync(0xffffffffu, acc2, 2);
                acc3 += __shfl_xor_sync(0xffffffffu, acc3, 1);
                acc3 += __shfl_xor_sync(0xffffffffu, acc3, 2);
                if ((lane & 3) == 0) {
                    int i = ch * 8 + wn * 4 + (nt >> 1);
                    out_s[er0 * 49 + i]        = acc0;
                    out_s[(er0 + 8) * 49 + i]  = acc1;
                    out_s[(er0 + 16) * 49 + i] = acc2;
                    out_s[(er0 + 24) * 49 + i] = acc3;
                }
                acc0 = 0.f; acc1 = 0.f; acc2 = 0.f; acc3 = 0.f;
            }
        }

        if (pf) {
            CPA_WAIT0();
            __syncthreads();
        }
    }
    __syncthreads();   // out_s complete; B buffers dead -> sc_s/v_s overlay

    // ---- per-edge: qkv = out48.reshape(24,2) @ b2f -> scores + v (to smem) ----
    float* sc_s = (float*)(smem + SV_SC);
    float* v_s  = (float*)(smem + SV_V);
    if (tid < 128) {
        int e = e0 + tid;
        const float* o48 = out_s + tid * 49;
        float bb[8];
#pragma unroll
        for (int x = 0; x < 8; ++x) bb[x] = b2[(size_t)e * 8 + x];

#pragma unroll
        for (int h = 0; h < 4; ++h) {
            float s = 0.f;
#pragma unroll
            for (int mm = 0; mm < 2; ++mm) {
                int m = 2 * h + mm;
#pragma unroll
                for (int d = 0; d < 4; ++d) {
                    float q = o48[m * 2]       * bb[d] + o48[m * 2 + 1]       * bb[4 + d];
                    float k = o48[(8 + m) * 2] * bb[d] + o48[(8 + m) * 2 + 1] * bb[4 + d];
                    s = fmaf(q, k, s);
                }
            }
            sc_s[tid * 4 + h] = s * 0.35355339059327376f;
        }
#pragma unroll
        for (int m = 0; m < 8; ++m)
#pragma unroll
            for (int d = 0; d < 4; ++d)
                v_s[tid * 32 + m * 4 + d] =
                    o48[(16 + m) * 2] * bb[d] + o48[(16 + m) * 2 + 1] * bb[4 + d];
    }
    __syncthreads();

    // ---- per-node attention: warp wid handles node blockIdx.x*8 + wid ----
    {
        float* outsm = (float*)(smem + S_TMP) + wid * 33;   // overlay on tmp_s
        int n = blockIdx.x * 8 + wid;
        int nb = wid * 16;

        float2 sc2 = *(float2*)&sc_s[nb * 4 + lane * 2];
        float s0 = sc2.x, s1 = sc2.y;

        float m0 = s0, m1 = s1;
#pragma unroll
        for (int off = 2; off < 32; off <<= 1) {
            m0 = fmaxf(m0, __shfl_xor_sync(0xffffffffu, m0, off));
            m1 = fmaxf(m1, __shfl_xor_sync(0xffffffffu, m1, off));
        }
        float e0v = expf(s0 - m0), e1v = expf(s1 - m1);
        float z0 = e0v, z1 = e1v;
#pragma unroll
        for (int off = 2; off < 32; off <<= 1) {
            z0 += __shfl_xor_sync(0xffffffffu, z0, off);
            z1 += __shfl_xor_sync(0xffffffffu, z1, off);
        }
        float a0 = e0v / z0, a1 = e1v / z1;

        const int m_mine = lane & 7;
        const int hsel   = (m_mine >> 1) & 1;
        float r[4] = {0.f, 0.f, 0.f, 0.f};
#pragma unroll
        for (int it = 0; it < 4; ++it) {
            float4 vv = *(float4*)&v_s[nb * 32 + it * 128 + lane * 4];
            int lsrc = 8 * it + ((lane >> 3) << 1) + ((lane >> 2) & 1);
            float av0 = __shfl_sync(0xffffffffu, a0, lsrc);
            float av1 = __shfl_sync(0xffffffffu, a1, lsrc);
            float a = hsel ? av1 : av0;
            r[0] = fmaf(a, vv.x, r[0]);
            r[1] = fmaf(a, vv.y, r[1]);
            r[2] = fmaf(a, vv.z, r[2]);
            r[3] = fmaf(a, vv.w, r[3]);
        }
#pragma unroll
        for (int off = 8; off < 32; off <<= 1)
#pragma unroll
            for (int d = 0; d < 4; ++d)
                r[d] += __shfl_xor_sync(0xffffffffu, r[d], off);

        if (lane < 8) {
#pragma unroll
            for (int d = 0; d < 4; ++d)
                outsm[m_mine * 4 + d] = r[d];
        }
        __syncwarp();

        int mm = lane >> 2, dd = lane & 3;
        int o = (dd == 0) ? mm : 8 + mm;
        float val = (dd == 0) ? bias[mm] : 0.f;
#pragma unroll
        for (int mp = 0; mp < 8; ++mp)
            val = fmaf(Wout[o * 8 + mp], outsm[mp * 4 + dd], val);
        out[(size_t)n * 32 + lane] = val;
    }
}

// ---------------- launcher ----------------------------------------------------
extern "C" void kernel_launch(void* const* d_in, const int* in_sizes, int n_in,
                              void* d_out, int out_size) {
    const float* b1   = (const float*)d_in[0];
    const float* b2   = (const float*)d_in[1];
    const float* ef   = (const float*)d_in[2];
    const float* f    = (const float*)d_in[3];
    const int*   nidx = (const int*)  d_in[4];
    const float* W1   = (const float*)d_in[5];
    const float* b1l  = (const float*)d_in[6];
    const float* W2   = (const float*)d_in[7];
    const float* b2l  = (const float*)d_in[8];
    const float* Wout = (const float*)d_in[9];
    const float* bias = (const float*)d_in[10];
    float* out = (float*)d_out;
    (void)in_sizes; (void)n_in; (void)out_size;

    cudaFuncSetAttribute(k2_fused, cudaFuncAttributeMaxDynamicSharedMemorySize, S_TOT);

    k0_prep<<<(768 * 64 + 255) / 256, 256>>>(W2, W1);
    k2_fused<<<NTILES, 256, S_TOT>>>(ef, b1l, f, nidx, b1, b2, b2l, Wout, bias, out);
}